// round 15
// baseline (speedup 1.0000x reference)
#include <cuda_runtime.h>
#include <cuda_bf16.h>
#include <cstdint>

// Problem constants
#define B_   1024
#define T_   128
#define OBS_ 256
#define LAT_ 64
#define BT_  (B_ * T_)   // 131072
#define STG  40960       // bytes per smem stage
#define SMEM_DYN (2 * STG)

// Sequential work-queue sizes
#define NS1 320   // S1: 160 tiles x ksplit2
#define NS2 256   // S2: 64 tiles x ksplit4
#define NS3 128   // fused S3/GRU: B/8 blocks
#define NTOT (NS1 + NS2 + NS3)

// ---------------------------------------------------------------------------
// Static device scratch
// ---------------------------------------------------------------------------
__device__ __nv_bfloat16 g_bufA_hi[(size_t)BT_ * 512];
__device__ __nv_bfloat16 g_bufA_lo[(size_t)BT_ * 512];
__device__ __nv_bfloat16 g_bufB_hi[(size_t)BT_ * 512];
__device__ __nv_bfloat16 g_bufB_lo[(size_t)BT_ * 512];
__device__ float         g_posc[(size_t)BT_ * 512];
__device__ __nv_bfloat16 g_z_hi[(size_t)BT_ * 64];
__device__ __nv_bfloat16 g_z_lo[(size_t)BT_ * 64];
__device__ float         g_s1p[2 * (size_t)B_ * 2560];   // S1 ksplit2 partials: [pri|pos|gh]
__device__ float         g_a1p[4 * (size_t)B_ * 1024];   // S2 ksplit4 partials
__device__ float         g_h[(size_t)B_ * 512];
__device__ __nv_bfloat16 g_h_hi[(size_t)B_ * 512];
__device__ __nv_bfloat16 g_h_lo[(size_t)B_ * 512];
__device__ float         g_wiht[64 * 1536];
__device__ float         g_w2t[512 * 256];
__device__ int           g_work[T_];
__device__ int           g_done1[T_];
__device__ int           g_done2[T_];

enum : int {
    OFF_encW0  = 0,
    OFF_encW1  = OFF_encW0  + 512 * 256,
    OFF_encW2  = OFF_encW1  + 512 * 512,
    OFF_posW0e = OFF_encW2  + 512 * 512,
    OFF_posW0h = OFF_posW0e + 512 * 512,
    OFF_priW0  = OFF_posW0h + 512 * 512,
    OFF_gruWhh = OFF_priW0  + 512 * 512,
    OFF_priW1  = OFF_gruWhh + 1536 * 512,
    OFF_posW1  = OFF_priW1  + 512 * 512,
    OFF_priW2  = OFF_posW1  + 512 * 512,
    OFF_posW2  = OFF_priW2  + 128 * 512,
    OFF_decW0  = OFF_posW2  + 128 * 512,
    OFF_decW1  = OFF_decW0  + 512 * 64,
    OFF_decW2  = OFF_decW1  + 512 * 512,
    WTOT       = OFF_decW2  + 256 * 512
};
__device__ __nv_bfloat16 g_whi[WTOT];
__device__ __nv_bfloat16 g_wlo[WTOT];

__device__ __forceinline__ float eluf(float x) { return x > 0.f ? x : expm1f(x); }

__device__ __forceinline__ uint32_t smem_u32(const void* p) {
    uint32_t a;
    asm("{ .reg .u64 t; cvta.to.shared.u64 t, %1; cvt.u32.u64 %0, t; }" : "=r"(a) : "l"(p));
    return a;
}
__device__ __forceinline__ void cpasync16(uint32_t saddr, const void* gptr) {
    asm volatile("cp.async.cg.shared.global [%0], [%1], 16;" :: "r"(saddr), "l"(gptr));
}
__device__ __forceinline__ void cp_commit() {
    asm volatile("cp.async.commit_group;" ::: "memory");
}
__device__ __forceinline__ void ldsm4(uint32_t* r, uint32_t addr) {
    asm volatile("ldmatrix.sync.aligned.m8n8.x4.shared.b16 {%0,%1,%2,%3}, [%4];"
                 : "=r"(r[0]), "=r"(r[1]), "=r"(r[2]), "=r"(r[3]) : "r"(addr));
}
__device__ __forceinline__ void mma_bf16(float* c, const uint32_t* a, uint32_t b0, uint32_t b1) {
    asm volatile(
        "mma.sync.aligned.m16n8k16.row.col.f32.bf16.bf16.f32 "
        "{%0,%1,%2,%3}, {%4,%5,%6,%7}, {%8,%9}, {%0,%1,%2,%3};"
        : "+f"(c[0]), "+f"(c[1]), "+f"(c[2]), "+f"(c[3])
        : "r"(a[0]), "r"(a[1]), "r"(a[2]), "r"(a[3]), "r"(b0), "r"(b1));
}

// ---------------------------------------------------------------------------
// Grouped GEMM descriptor
// am: 0 = A fp32, 1 = A bf16 pairs (cp.async), 2 = A = elu(Af + Af2) fp32
// ---------------------------------------------------------------------------
struct GemmTC {
    const float*         Af[3];
    const float*         Af2[3];
    const __nv_bfloat16* Ahi[3];
    const __nv_bfloat16* Alo[3];
    int                  lda[3];
    const __nv_bfloat16* Whi[3];
    const __nv_bfloat16* Wlo[3];
    const float*         bias[3];
    const float*         add[3];
    long                 ldadd[3];
    float*               Cf[3];
    __nv_bfloat16*       Chi[3];
    __nv_bfloat16*       Clo[3];
    int                  ldc[3];
    int                  act[3];
    int                  mode[3];
    int                  n_off[4];
    int K, ng, ksplit;
    long csplit;
};

// 128x128 tile body. Called with explicit (n0, m0, kz).
__device__ __forceinline__ void tile_body(const GemmTC& d, int am,
                                          int n0, int m0, int kz, char* smem) {
    const uint32_t sb = smem_u32(smem);
    const int tid = threadIdx.x;
    const int wid = tid >> 5;
    const int lane = tid & 31;
    const int warp_m = wid & 1;
    const int warp_n = wid >> 1;

    int g = 0;
    while (g + 1 < d.ng && n0 >= d.n_off[g + 1]) g++;
    const int nl0 = n0 - d.n_off[g];
    const int ldw = d.K;
    const int Ks = d.K / d.ksplit;
    const int kbase = kz * Ks;
    const int NC = Ks >> 5;

    const float*         Af  = (am != 1) ? d.Af[g] + kbase : nullptr;
    const float*         Af2 = (am == 2) ? d.Af2[g] + kbase : nullptr;
    const __nv_bfloat16* Ahi = (am == 1) ? d.Ahi[g] + kbase : nullptr;
    const __nv_bfloat16* Alo = (am == 1) ? d.Alo[g] + kbase : nullptr;
    const int lda = d.lda[g];
    const __nv_bfloat16* Whi = d.Whi[g] + (size_t)nl0 * ldw + kbase;
    const __nv_bfloat16* Wlo = d.Wlo[g] + (size_t)nl0 * ldw + kbase;

    float acc[4][4][4];
#pragma unroll
    for (int i = 0; i < 4; i++)
#pragma unroll
        for (int j = 0; j < 4; j++)
#pragma unroll
            for (int q = 0; q < 4; q++) acc[i][j][q] = 0.f;

    auto issueW = [&](int kc) {
        const uint32_t st = sb + (kc & 1) * STG;
        const int k0 = kc << 5;
#pragma unroll
        for (int i = 0; i < 2; i++) {
            const int idx = tid + i * 256;
            const int row = idx >> 2, ch = idx & 3;
            const uint32_t so = st + 20480 + row * 80 + ch * 16;
            cpasync16(so,         Whi + (size_t)row * ldw + k0 + ch * 8);
            cpasync16(so + 10240, Wlo + (size_t)row * ldw + k0 + ch * 8);
        }
    };
    auto issueA_pairs = [&](int kc) {
        const uint32_t st = sb + (kc & 1) * STG;
        const int k0 = kc << 5;
#pragma unroll
        for (int i = 0; i < 2; i++) {
            const int idx = tid + i * 256;
            const int row = idx >> 2, ch = idx & 3;
            const uint32_t so = st + row * 80 + ch * 16;
            cpasync16(so,         Ahi + (size_t)(m0 + row) * lda + k0 + ch * 8);
            cpasync16(so + 10240, Alo + (size_t)(m0 + row) * lda + k0 + ch * 8);
        }
    };

    auto cvt_store = [&](char* stp, int row, int col,
                         float x0, float x1, float x2, float x3) {
        __nv_bfloat162 h01 = __floats2bfloat162_rn(x0, x1);
        __nv_bfloat162 h23 = __floats2bfloat162_rn(x2, x3);
        __nv_bfloat162 l01 = __floats2bfloat162_rn(x0 - __bfloat162float(h01.x),
                                                   x1 - __bfloat162float(h01.y));
        __nv_bfloat162 l23 = __floats2bfloat162_rn(x2 - __bfloat162float(h23.x),
                                                   x3 - __bfloat162float(h23.y));
        const int bo = row * 80 + col * 2;
        *reinterpret_cast<uint2*>(stp + bo) =
            make_uint2(*reinterpret_cast<uint32_t*>(&h01), *reinterpret_cast<uint32_t*>(&h23));
        *reinterpret_cast<uint2*>(stp + 10240 + bo) =
            make_uint2(*reinterpret_cast<uint32_t*>(&l01), *reinterpret_cast<uint32_t*>(&l23));
    };

    float av[16];
    auto ldgA = [&](int kc) {
        const int k0 = kc << 5;
#pragma unroll
        for (int i = 0; i < 4; i++) {
            const int idx = tid + i * 256;
            const int row = idx >> 3, col = (idx & 7) * 4;
            const float4 v = *reinterpret_cast<const float4*>(
                Af + (size_t)(m0 + row) * lda + k0 + col);
            av[i * 4 + 0] = v.x; av[i * 4 + 1] = v.y;
            av[i * 4 + 2] = v.z; av[i * 4 + 3] = v.w;
        }
    };
    auto storeA = [&](int kc) {
        char* stp = smem + (kc & 1) * STG;
#pragma unroll
        for (int i = 0; i < 4; i++) {
            const int idx = tid + i * 256;
            const int row = idx >> 3, col = (idx & 7) * 4;
            cvt_store(stp, row, col, av[i * 4 + 0], av[i * 4 + 1], av[i * 4 + 2], av[i * 4 + 3]);
        }
    };
    auto storeA2 = [&](int kc) {
        char* stp = smem + (kc & 1) * STG;
        const int k0 = kc << 5;
#pragma unroll
        for (int i = 0; i < 4; i++) {
            const int idx = tid + i * 256;
            const int row = idx >> 3, col = (idx & 7) * 4;
            const size_t go = (size_t)(m0 + row) * lda + k0 + col;
            const float4 v0 = *reinterpret_cast<const float4*>(Af + go);
            const float4 v1 = *reinterpret_cast<const float4*>(Af2 + go);
            cvt_store(stp, row, col,
                      eluf(v0.x + v1.x), eluf(v0.y + v1.y),
                      eluf(v0.z + v1.z), eluf(v0.w + v1.w));
        }
    };

    const int lane15 = lane & 15;
    const int koff = (lane >> 4) << 3;
    const uint32_t arow = (uint32_t)(warp_m * 64 + lane15);
    const uint32_t brow = (uint32_t)(warp_n * 32 + lane15);

    auto compute = [&](int kc) {
        const uint32_t stb = sb + (kc & 1) * STG;
#pragma unroll
        for (int ks = 0; ks < 32; ks += 16) {
            const uint32_t acol = (uint32_t)(ks + koff) * 2;
            uint32_t ah[4][4], al[4][4];
#pragma unroll
            for (int mf = 0; mf < 4; mf++) {
                const uint32_t ad = stb + (arow + mf * 16) * 80 + acol;
                ldsm4(ah[mf], ad);
                ldsm4(al[mf], ad + 10240);
            }
#pragma unroll
            for (int nfp = 0; nfp < 2; nfp++) {
                const uint32_t bd = stb + 20480 + (brow + nfp * 16) * 80 + acol;
                uint32_t bh[4], bl[4];
                ldsm4(bh, bd);
                ldsm4(bl, bd + 10240);
#pragma unroll
                for (int j = 0; j < 2; j++) {
                    const int nf = nfp * 2 + j;
                    const uint32_t bh0 = bh[j], bh1 = bh[2 + j];
                    const uint32_t bl0 = bl[j], bl1 = bl[2 + j];
#pragma unroll
                    for (int mf = 0; mf < 4; mf++)
                        mma_bf16(acc[mf][nf], ah[mf], bh0, bh1);
#pragma unroll
                    for (int mf = 0; mf < 4; mf++)
                        mma_bf16(acc[mf][nf], ah[mf], bl0, bl1);
#pragma unroll
                    for (int mf = 0; mf < 4; mf++)
                        mma_bf16(acc[mf][nf], al[mf], bh0, bh1);
                }
            }
        }
    };

    if (am == 1) {
        issueA_pairs(0); issueW(0); cp_commit();
        for (int kc = 0; kc < NC; kc++) {
            if (kc + 1 < NC) { issueA_pairs(kc + 1); issueW(kc + 1); cp_commit(); }
            if (kc + 1 < NC) asm volatile("cp.async.wait_group 1;" ::: "memory");
            else             asm volatile("cp.async.wait_group 0;" ::: "memory");
            __syncthreads();
            compute(kc);
            __syncthreads();
        }
    } else if (am == 0) {
        ldgA(0);
        issueW(0); cp_commit();
        for (int kc = 0; kc < NC; kc++) {
            storeA(kc);
            if (kc + 1 < NC) { issueW(kc + 1); cp_commit(); }
            if (kc + 1 < NC) asm volatile("cp.async.wait_group 1;" ::: "memory");
            else             asm volatile("cp.async.wait_group 0;" ::: "memory");
            __syncthreads();
            if (kc + 1 < NC) ldgA(kc + 1);
            compute(kc);
            __syncthreads();
        }
    } else {
        issueW(0); cp_commit();
        for (int kc = 0; kc < NC; kc++) {
            if (kc + 1 < NC) { issueW(kc + 1); cp_commit(); }
            storeA2(kc);
            if (kc + 1 < NC) asm volatile("cp.async.wait_group 1;" ::: "memory");
            else             asm volatile("cp.async.wait_group 0;" ::: "memory");
            __syncthreads();
            compute(kc);
            __syncthreads();
        }
    }

    const float* bias = (kz == 0) ? d.bias[g] : nullptr;
    const float* add  = (kz == 0) ? d.add[g] : nullptr;
    const long ldadd  = d.ldadd[g];
    const int act     = d.act[g];
    const int mode    = d.mode[g];
    const int ldc     = d.ldc[g];
    float* Cf         = d.Cf[g] + (size_t)kz * d.csplit;
    __nv_bfloat16* Chi = d.Chi[g];
    __nv_bfloat16* Clo = d.Clo[g];

    const int gid = lane >> 2;
    const int tig = lane & 3;
#pragma unroll
    for (int mf = 0; mf < 4; mf++) {
        const int r0 = m0 + warp_m * 64 + mf * 16 + gid;
#pragma unroll
        for (int nf = 0; nf < 4; nf++) {
            const int coll = nl0 + warp_n * 32 + nf * 8 + tig * 2;
            float v0 = acc[mf][nf][0], v1 = acc[mf][nf][1];
            float v2 = acc[mf][nf][2], v3 = acc[mf][nf][3];
            if (bias) {
                const float b0v = bias[coll], b1v = bias[coll + 1];
                v0 += b0v; v1 += b1v; v2 += b0v; v3 += b1v;
            }
            if (add) {
                const float2 a0 = *reinterpret_cast<const float2*>(add + (size_t)r0 * ldadd + coll);
                const float2 a1 = *reinterpret_cast<const float2*>(add + (size_t)(r0 + 8) * ldadd + coll);
                v0 += a0.x; v1 += a0.y; v2 += a1.x; v3 += a1.y;
            }
            if (act) { v0 = eluf(v0); v1 = eluf(v1); v2 = eluf(v2); v3 = eluf(v3); }
            if (mode == 0) {
                *reinterpret_cast<float2*>(Cf + (size_t)r0 * ldc + coll)       = make_float2(v0, v1);
                *reinterpret_cast<float2*>(Cf + (size_t)(r0 + 8) * ldc + coll) = make_float2(v2, v3);
            } else {
                __nv_bfloat162 h0 = __floats2bfloat162_rn(v0, v1);
                __nv_bfloat162 l0 = __floats2bfloat162_rn(v0 - __bfloat162float(h0.x),
                                                          v1 - __bfloat162float(h0.y));
                __nv_bfloat162 h1 = __floats2bfloat162_rn(v2, v3);
                __nv_bfloat162 l1 = __floats2bfloat162_rn(v2 - __bfloat162float(h1.x),
                                                          v3 - __bfloat162float(h1.y));
                *reinterpret_cast<uint32_t*>(Chi + (size_t)r0 * ldc + coll)       = *reinterpret_cast<uint32_t*>(&h0);
                *reinterpret_cast<uint32_t*>(Clo + (size_t)r0 * ldc + coll)       = *reinterpret_cast<uint32_t*>(&l0);
                *reinterpret_cast<uint32_t*>(Chi + (size_t)(r0 + 8) * ldc + coll) = *reinterpret_cast<uint32_t*>(&h1);
                *reinterpret_cast<uint32_t*>(Clo + (size_t)(r0 + 8) * ldc + coll) = *reinterpret_cast<uint32_t*>(&l1);
            }
        }
    }
}

template <int AMODE>
__global__ void __launch_bounds__(256, 2) gemm_tc(GemmTC d) {
    extern __shared__ char smem[];
    const int kz = (d.ksplit > 1) ? (int)blockIdx.z : 0;
    tile_body(d, AMODE, blockIdx.x * 128, blockIdx.y * 128, kz, smem);
}

// ---------------------------------------------------------------------------
// Fused S3 + latent + GRU body (256 threads, TMB = 8 rows)
// Sums 4 a1p partials; gh = sum of 2 s1p partials.
// ---------------------------------------------------------------------------
#define A1_PB ((size_t)B_ * 1024)
#define S1_PB ((size_t)B_ * 2560)
struct SeqP {
    const float* eps;
    const float* bih;
    const float* pri_b2;
    const float* pos_b2;
    float* kls;
    float* mu;
    int t;
};

__device__ __forceinline__ void s3_body(const SeqP& sp, int m0, char* smem) {
    float (*sA)[1024]   = reinterpret_cast<float(*)[1024]>(smem);
    float (*s_out2)[256] = reinterpret_cast<float(*)[256]>(smem + 32768);
    float (*zs)[64]     = reinterpret_cast<float(*)[64]>(smem + 32768 + 8192);
    float (*klw)[2]     = reinterpret_cast<float(*)[2]>(smem + 32768 + 8192 + 2048);

    const int tid = threadIdx.x;  // 256 threads
    const int t = sp.t;

    // Phase 1: sA = elu(sum of 4 S2 partials)
#pragma unroll
    for (int i = 0; i < 8; i++) {
        const int idx = tid + i * 256;
        const int row = idx >> 8, c4 = (idx & 255) * 4;
        const size_t go = (size_t)(m0 + row) * 1024 + c4;
        const float4 v0 = *reinterpret_cast<const float4*>(g_a1p + go);
        const float4 v1 = *reinterpret_cast<const float4*>(g_a1p + A1_PB + go);
        const float4 v2 = *reinterpret_cast<const float4*>(g_a1p + 2 * A1_PB + go);
        const float4 v3 = *reinterpret_cast<const float4*>(g_a1p + 3 * A1_PB + go);
        sA[row][c4 + 0] = eluf(v0.x + v1.x + v2.x + v3.x);
        sA[row][c4 + 1] = eluf(v0.y + v1.y + v2.y + v3.y);
        sA[row][c4 + 2] = eluf(v0.z + v1.z + v2.z + v3.z);
        sA[row][c4 + 3] = eluf(v0.w + v1.w + v2.w + v3.w);
    }
    __syncthreads();

    // Phase 2: out2[r][c] = sum_k A[r][aoff+k] * W2t[k][c], full K per thread
    {
        const int c = tid;
        const int aoff = (c < 128) ? 0 : 512;
        const float* wp = g_w2t + c;
        float accs[8];
#pragma unroll
        for (int r = 0; r < 8; r++) accs[r] = 0.f;
#pragma unroll 2
        for (int kk = 0; kk < 128; kk++) {
            const float w0 = wp[(kk * 4 + 0) * 256];
            const float w1 = wp[(kk * 4 + 1) * 256];
            const float w2 = wp[(kk * 4 + 2) * 256];
            const float w3 = wp[(kk * 4 + 3) * 256];
#pragma unroll
            for (int r = 0; r < 8; r++) {
                const float4 av = *reinterpret_cast<const float4*>(&sA[r][aoff + kk * 4]);
                accs[r] = fmaf(av.x, w0, fmaf(av.y, w1, fmaf(av.z, w2, fmaf(av.w, w3, accs[r]))));
            }
        }
        const float b = (c < 128) ? sp.pri_b2[c] : sp.pos_b2[c - 128];
#pragma unroll
        for (int r = 0; r < 8; r++) s_out2[r][c] = accs[r] + b;
    }
    __syncthreads();

    // Phase 3: latent sample + KL + mu (2 passes of 256)
#pragma unroll
    for (int p = 0; p < 2; p++) {
        const int idx = tid + p * 256;
        const int r = idx >> 6, k = idx & 63;
        const int m = m0 + r;
        const float mu_p = s_out2[r][k];
        const float ls_p = s_out2[r][64 + k];
        const float mu_q = s_out2[r][128 + k];
        const float ls_q = s_out2[r][192 + k];
        const float e = sp.eps[((size_t)m * T_ + t) * 64 + k];
        const float zl = fmaf(expf(ls_q), e, mu_q);
        zs[r][k] = zl;
        const __nv_bfloat16 zh = __float2bfloat16(zl);
        g_z_hi[((size_t)m * T_ + t) * 64 + k] = zh;
        g_z_lo[((size_t)m * T_ + t) * 64 + k] = __float2bfloat16(zl - __bfloat162float(zh));
        sp.mu[((size_t)m * T_ + t) * 64 + k] = mu_q;
        const float dm = mu_q - mu_p;
        float klv = ls_p - ls_q + (expf(2.f * ls_q) + dm * dm) / (2.f * expf(2.f * ls_p)) - 0.5f;
#pragma unroll
        for (int off = 16; off > 0; off >>= 1)
            klv += __shfl_down_sync(0xffffffffu, klv, off);
        if ((idx & 31) == 0) klw[r][(idx >> 5) & 1] = klv;
    }
    __syncthreads();
    if (tid < 8) sp.kls[(size_t)(m0 + tid) * T_ + t] = klw[tid][0] + klw[tid][1];

    // Phase 4: GRU gates + h update, 2 columns per thread
#pragma unroll 1
    for (int jj = 0; jj < 2; jj++) {
        const int j = tid + jj * 256;
        float ar[8], az[8], an[8];
#pragma unroll
        for (int r = 0; r < 8; r++) { ar[r] = 0.f; az[r] = 0.f; an[r] = 0.f; }
#pragma unroll 4
        for (int k = 0; k < 64; k++) {
            const float wr = g_wiht[k * 1536 + j];
            const float wz = g_wiht[k * 1536 + 512 + j];
            const float wn = g_wiht[k * 1536 + 1024 + j];
#pragma unroll
            for (int r = 0; r < 8; r++) {
                const float zk = zs[r][k];
                ar[r] = fmaf(zk, wr, ar[r]);
                az[r] = fmaf(zk, wz, az[r]);
                an[r] = fmaf(zk, wn, an[r]);
            }
        }
        const float br = sp.bih[j], bz = sp.bih[512 + j], bn = sp.bih[1024 + j];
#pragma unroll
        for (int r = 0; r < 8; r++) {
            const int m = m0 + r;
            const float* g0 = g_s1p + (size_t)m * 2560 + 1024;
            const float ghr = g0[j]        + g0[S1_PB + j];
            const float ghz = g0[512 + j]  + g0[S1_PB + 512 + j];
            const float ghn = g0[1024 + j] + g0[S1_PB + 1024 + j];
            const float rg = 1.f / (1.f + expf(-(ar[r] + br + ghr)));
            const float zg = 1.f / (1.f + expf(-(az[r] + bz + ghz)));
            const float ng = tanhf(an[r] + bn + rg * ghn);
            const float hv = g_h[(size_t)m * 512 + j];
            const float hn = (1.f - zg) * ng + zg * hv;
            g_h[(size_t)m * 512 + j] = hn;
            const __nv_bfloat16 hh = __float2bfloat16(hn);
            g_h_hi[(size_t)m * 512 + j] = hh;
            g_h_lo[(size_t)m * 512 + j] = __float2bfloat16(hn - __bfloat162float(hh));
        }
    }
}

// ---------------------------------------------------------------------------
// One launch per timestep: ordered work queue S1 -> S2 -> S3/GRU.
// ---------------------------------------------------------------------------
__global__ void __launch_bounds__(256, 2) seq_step(GemmTC d1, GemmTC d2, SeqP sp) {
    extern __shared__ char smem[];
    __shared__ int s_item;
    const int t = sp.t;

    while (true) {
        if (threadIdx.x == 0) s_item = atomicAdd(&g_work[t], 1);
        __syncthreads();
        const int it = s_item;
        if (it >= NTOT) break;

        if (it < NS1) {
            const int kz = it / 160, rem = it % 160;
            tile_body(d1, 1, (rem % 20) * 128, (rem / 20) * 128, kz, smem);
            __threadfence();
            __syncthreads();
            if (threadIdx.x == 0) atomicAdd(&g_done1[t], 1);
        } else if (it < NS1 + NS2) {
            if (threadIdx.x == 0) {
                while (*(volatile int*)&g_done1[t] < NS1) __nanosleep(128);
                __threadfence();
            }
            __syncthreads();
            const int j = it - NS1, kz = j / 64, rem = j % 64;
            tile_body(d2, 2, (rem % 8) * 128, (rem / 8) * 128, kz, smem);
            __threadfence();
            __syncthreads();
            if (threadIdx.x == 0) atomicAdd(&g_done2[t], 1);
        } else {
            if (threadIdx.x == 0) {
                while (*(volatile int*)&g_done2[t] < NS2) __nanosleep(128);
                __threadfence();
            }
            __syncthreads();
            s3_body(sp, (it - NS1 - NS2) * 8, smem);
        }
        __syncthreads();
    }
}

// ---------------------------------------------------------------------------
// Init/pack: weights (hi/lo), Wih^T, W2^T, zero h, zero queue counters
// ---------------------------------------------------------------------------
struct PackArgs {
    const float* src[14];
    int ld[14];
    int coff[14];
    const float* wih;
};
__constant__ int c_seg_off[15] = {
    OFF_encW0, OFF_encW1, OFF_encW2, OFF_posW0e, OFF_posW0h, OFF_priW0,
    OFF_gruWhh, OFF_priW1, OFF_posW1, OFF_priW2, OFF_posW2, OFF_decW0,
    OFF_decW1, OFF_decW2, WTOT
};
__constant__ int c_seg_K[14] = {
    256, 512, 512, 512, 512, 512, 512, 512, 512, 512, 512, 64, 512, 512
};

#define PACK_EXTRA (64 * 1536 + B_ * 512 + 512 * 256 + 3 * T_)
__global__ void pack_all(PackArgs a) {
    const int i = blockIdx.x * 256 + threadIdx.x;
    if (i < WTOT) {
        int s = 0;
        while (s + 1 < 14 && i >= c_seg_off[s + 1]) s++;
        const int li = i - c_seg_off[s];
        const int K = c_seg_K[s];
        const int r = li / K, k = li - r * K;
        const float v = a.src[s][(size_t)r * a.ld[s] + a.coff[s] + k];
        const __nv_bfloat16 h = __float2bfloat16(v);
        g_whi[i] = h;
        g_wlo[i] = __float2bfloat16(v - __bfloat162float(h));
    } else if (i < WTOT + 64 * 1536) {
        const int li = i - WTOT;
        const int row = li / 64, k = li - row * 64;
        g_wiht[k * 1536 + row] = a.wih[li];
    } else if (i < WTOT + 64 * 1536 + B_ * 512) {
        const int li = i - WTOT - 64 * 1536;
        g_h[li] = 0.f;
        g_h_hi[li] = __float2bfloat16(0.f);
        g_h_lo[li] = __float2bfloat16(0.f);
    } else if (i < WTOT + 64 * 1536 + B_ * 512 + 512 * 256) {
        const int li = i - WTOT - 64 * 1536 - B_ * 512;
        const int k = li >> 8, c = li & 255;
        g_w2t[li] = (c < 128) ? a.src[9][(size_t)c * 512 + k]
                              : a.src[10][(size_t)(c - 128) * 512 + k];
    } else if (i < WTOT + 64 * 1536 + B_ * 512 + 512 * 256 + 3 * T_) {
        const int li = i - WTOT - 64 * 1536 - B_ * 512 - 512 * 256;
        if (li < T_)           g_work[li] = 0;
        else if (li < 2 * T_)  g_done1[li - T_] = 0;
        else                   g_done2[li - 2 * T_] = 0;
    }
}

// ---------------------------------------------------------------------------
// Host helpers
// ---------------------------------------------------------------------------
static inline GemmTC make_desc(int K, int ksplit = 1, long csplit = 0) {
    GemmTC d{};
    d.K = K; d.ng = 0; d.n_off[0] = 0;
    d.ksplit = ksplit; d.csplit = csplit;
    return d;
}
static inline void add_group(GemmTC& d, int nsub,
                             const float* Af, const float* Af2,
                             const __nv_bfloat16* Ahi, const __nv_bfloat16* Alo, int lda,
                             const __nv_bfloat16* Whi, const __nv_bfloat16* Wlo,
                             const float* bias, const float* add, long ldadd, int act,
                             int mode, float* Cf, __nv_bfloat16* Chi, __nv_bfloat16* Clo, int ldc) {
    const int g = d.ng;
    d.Af[g] = Af; d.Af2[g] = Af2; d.Ahi[g] = Ahi; d.Alo[g] = Alo; d.lda[g] = lda;
    d.Whi[g] = Whi; d.Wlo[g] = Wlo;
    d.bias[g] = bias; d.add[g] = add; d.ldadd[g] = ldadd;
    d.act[g] = act; d.mode[g] = mode;
    d.Cf[g] = Cf; d.Chi[g] = Chi; d.Clo[g] = Clo; d.ldc[g] = ldc;
    d.n_off[g + 1] = d.n_off[g] + nsub;
    d.ng = g + 1;
}

extern "C" void kernel_launch(void* const* d_in, const int* in_sizes, int n_in,
                              void* d_out, int out_size) {
    const float* obs     = (const float*)d_in[0];
    const float* eps     = (const float*)d_in[1];
    const float* enc_W0  = (const float*)d_in[2];
    const float* enc_b0  = (const float*)d_in[3];
    const float* enc_W1  = (const float*)d_in[4];
    const float* enc_b1  = (const float*)d_in[5];
    const float* enc_W2  = (const float*)d_in[6];
    const float* enc_b2  = (const float*)d_in[7];
    const float* pri_W0  = (const float*)d_in[8];
    const float* pri_b0  = (const float*)d_in[9];
    const float* pri_W1  = (const float*)d_in[10];
    const float* pri_b1  = (const float*)d_in[11];
    const float* pri_W2  = (const float*)d_in[12];
    const float* pri_b2  = (const float*)d_in[13];
    const float* pos_W0  = (const float*)d_in[14];
    const float* pos_b0  = (const float*)d_in[15];
    const float* pos_W1  = (const float*)d_in[16];
    const float* pos_b1  = (const float*)d_in[17];
    const float* pos_W2  = (const float*)d_in[18];
    const float* pos_b2  = (const float*)d_in[19];
    const float* dec_W0  = (const float*)d_in[20];
    const float* dec_b0  = (const float*)d_in[21];
    const float* dec_W1  = (const float*)d_in[22];
    const float* dec_b1  = (const float*)d_in[23];
    const float* dec_W2  = (const float*)d_in[24];
    const float* dec_b2  = (const float*)d_in[25];
    const float* gru_Wih = (const float*)d_in[26];
    const float* gru_bih = (const float*)d_in[27];
    const float* gru_Whh = (const float*)d_in[28];
    const float* gru_bhh = (const float*)d_in[29];
    (void)in_sizes; (void)n_in; (void)out_size;

    __nv_bfloat16 *bufA_hi, *bufA_lo, *bufB_hi, *bufB_lo, *z_hi, *z_lo;
    __nv_bfloat16 *whi, *wlo, *h_hi, *h_lo;
    float *posc, *s1p, *a1p;
    cudaGetSymbolAddress((void**)&bufA_hi, g_bufA_hi);
    cudaGetSymbolAddress((void**)&bufA_lo, g_bufA_lo);
    cudaGetSymbolAddress((void**)&bufB_hi, g_bufB_hi);
    cudaGetSymbolAddress((void**)&bufB_lo, g_bufB_lo);
    cudaGetSymbolAddress((void**)&z_hi,    g_z_hi);
    cudaGetSymbolAddress((void**)&z_lo,    g_z_lo);
    cudaGetSymbolAddress((void**)&posc,    g_posc);
    cudaGetSymbolAddress((void**)&whi,     g_whi);
    cudaGetSymbolAddress((void**)&wlo,     g_wlo);
    cudaGetSymbolAddress((void**)&s1p,     g_s1p);
    cudaGetSymbolAddress((void**)&a1p,     g_a1p);
    cudaGetSymbolAddress((void**)&h_hi,    g_h_hi);
    cudaGetSymbolAddress((void**)&h_lo,    g_h_lo);

    cudaFuncSetAttribute(gemm_tc<0>, cudaFuncAttributeMaxDynamicSharedMemorySize, SMEM_DYN);
    cudaFuncSetAttribute(gemm_tc<1>, cudaFuncAttributeMaxDynamicSharedMemorySize, SMEM_DYN);
    cudaFuncSetAttribute(seq_step,   cudaFuncAttributeMaxDynamicSharedMemorySize, SMEM_DYN);

    float* recons = (float*)d_out;
    float* kls    = recons + (size_t)BT_ * OBS_;
    float* mu     = kls + BT_;

    // ---- single init/pack launch ----
    PackArgs pa;
    const float* srcs[14] = { enc_W0, enc_W1, enc_W2, pos_W0, pos_W0, pri_W0, gru_Whh,
                              pri_W1, pos_W1, pri_W2, pos_W2, dec_W0, dec_W1, dec_W2 };
    const int lds[14]   = { 256, 512, 512, 1024, 1024, 512, 512, 512, 512, 512, 512, 64, 512, 512 };
    const int coffs[14] = { 0, 0, 0, 512, 0, 0, 0, 0, 0, 0, 0, 0, 0, 0 };
    for (int i = 0; i < 14; i++) { pa.src[i] = srcs[i]; pa.ld[i] = lds[i]; pa.coff[i] = coffs[i]; }
    pa.wih = gru_Wih;
    pack_all<<<(WTOT + PACK_EXTRA + 255) / 256, 256>>>(pa);

    // ---- Encoder chain (parallel over B*T) ----
    {
        GemmTC d = make_desc(256);
        add_group(d, 512, obs, nullptr, nullptr, nullptr, 256, whi + OFF_encW0, wlo + OFF_encW0,
                  enc_b0, nullptr, 0, 1, 1, nullptr, bufA_hi, bufA_lo, 512);
        gemm_tc<0><<<dim3(4, BT_ / 128), 256, SMEM_DYN>>>(d);
    }
    {
        GemmTC d = make_desc(512);
        add_group(d, 512, nullptr, nullptr, bufA_hi, bufA_lo, 512, whi + OFF_encW1, wlo + OFF_encW1,
                  enc_b1, nullptr, 0, 1, 1, nullptr, bufB_hi, bufB_lo, 512);
        gemm_tc<1><<<dim3(4, BT_ / 128), 256, SMEM_DYN>>>(d);
    }
    {
        GemmTC d = make_desc(512);
        add_group(d, 512, nullptr, nullptr, bufB_hi, bufB_lo, 512, whi + OFF_encW2, wlo + OFF_encW2,
                  enc_b2, nullptr, 0, 0, 1, nullptr, bufA_hi, bufA_lo, 512);
        gemm_tc<1><<<dim3(4, BT_ / 128), 256, SMEM_DYN>>>(d);
    }
    {
        GemmTC d = make_desc(512);
        add_group(d, 512, nullptr, nullptr, bufA_hi, bufA_lo, 512, whi + OFF_posW0e, wlo + OFF_posW0e,
                  pos_b0, nullptr, 0, 0, 0, posc, nullptr, nullptr, 512);
        gemm_tc<1><<<dim3(4, BT_ / 128), 256, SMEM_DYN>>>(d);
    }

    // ---- Sequential recurrence: ONE launch per step ----
    for (int t = 0; t < T_; t++) {
        GemmTC d1 = make_desc(512, 2, (long)B_ * 2560);
        add_group(d1, 512, nullptr, nullptr, h_hi, h_lo, 512, whi + OFF_priW0, wlo + OFF_priW0,
                  pri_b0, nullptr, 0, 0, 0, s1p, nullptr, nullptr, 2560);
        add_group(d1, 512, nullptr, nullptr, h_hi, h_lo, 512, whi + OFF_posW0h, wlo + OFF_posW0h,
                  nullptr, posc + (size_t)t * 512, (long)T_ * 512, 0,
                  0, s1p + 512, nullptr, nullptr, 2560);
        add_group(d1, 1536, nullptr, nullptr, h_hi, h_lo, 512, whi + OFF_gruWhh, wlo + OFF_gruWhh,
                  gru_bhh, nullptr, 0, 0, 0, s1p + 1024, nullptr, nullptr, 2560);

        GemmTC d2 = make_desc(512, 4, (long)B_ * 1024);
        add_group(d2, 512, s1p, s1p + (size_t)B_ * 2560, nullptr, nullptr, 2560,
                  whi + OFF_priW1, wlo + OFF_priW1,
                  pri_b1, nullptr, 0, 0, 0, a1p, nullptr, nullptr, 1024);
        add_group(d2, 512, s1p + 512, s1p + (size_t)B_ * 2560 + 512, nullptr, nullptr, 2560,
                  whi + OFF_posW1, wlo + OFF_posW1,
                  pos_b1, nullptr, 0, 0, 0, a1p + 512, nullptr, nullptr, 1024);

        SeqP sp;
        sp.eps = eps; sp.bih = gru_bih;
        sp.pri_b2 = pri_b2; sp.pos_b2 = pos_b2;
        sp.kls = kls; sp.mu = mu; sp.t = t;

        seq_step<<<296, 256, SMEM_DYN>>>(d1, d2, sp);
    }

    // ---- Deferred decoder over all (B*T) rows ----
    {
        GemmTC d = make_desc(64);
        add_group(d, 512, nullptr, nullptr, z_hi, z_lo, 64, whi + OFF_decW0, wlo + OFF_decW0,
                  dec_b0, nullptr, 0, 1, 1, nullptr, bufA_hi, bufA_lo, 512);
        gemm_tc<1><<<dim3(4, BT_ / 128), 256, SMEM_DYN>>>(d);
    }
    {
        GemmTC d = make_desc(512);
        add_group(d, 512, nullptr, nullptr, bufA_hi, bufA_lo, 512, whi + OFF_decW1, wlo + OFF_decW1,
                  dec_b1, nullptr, 0, 1, 1, nullptr, bufB_hi, bufB_lo, 512);
        gemm_tc<1><<<dim3(4, BT_ / 128), 256, SMEM_DYN>>>(d);
    }
    {
        GemmTC d = make_desc(512);
        add_group(d, 256, nullptr, nullptr, bufB_hi, bufB_lo, 512, whi + OFF_decW2, wlo + OFF_decW2,
                  dec_b2, nullptr, 0, 0, 0, recons, nullptr, nullptr, 256);
        gemm_tc<1><<<dim3(2, BT_ / 128), 256, SMEM_DYN>>>(d);
    }
}

// round 16
// speedup vs baseline: 1.2338x; 1.2338x over previous
#include <cuda_runtime.h>
#include <cuda_bf16.h>
#include <cstdint>

// Problem constants
#define B_   1024
#define T_   128
#define OBS_ 256
#define LAT_ 64
#define BT_  (B_ * T_)   // 131072
#define STG  40960       // bytes per smem stage (4 arrays x 128 rows x 80B)
#define SMEM_DYN (2 * STG)

// ---------------------------------------------------------------------------
// Static device scratch
// ---------------------------------------------------------------------------
__device__ __nv_bfloat16 g_bufA_hi[(size_t)BT_ * 512];
__device__ __nv_bfloat16 g_bufA_lo[(size_t)BT_ * 512];
__device__ __nv_bfloat16 g_bufB_hi[(size_t)BT_ * 512];
__device__ __nv_bfloat16 g_bufB_lo[(size_t)BT_ * 512];
__device__ float         g_posc[(size_t)BT_ * 512];
__device__ __nv_bfloat16 g_z_hi[(size_t)BT_ * 64];
__device__ __nv_bfloat16 g_z_lo[(size_t)BT_ * 64];
__device__ float         g_s1p[2 * (size_t)B_ * 2560];   // S1 split-K partials: [pri|pos|gh]
__device__ float         g_a1p[4 * (size_t)B_ * 1024];   // S2 split-K partials
__device__ float         g_h[(size_t)B_ * 512];
__device__ __nv_bfloat16 g_h_hi[(size_t)B_ * 512];
__device__ __nv_bfloat16 g_h_lo[(size_t)B_ * 512];
__device__ float         g_wiht[64 * 1536];
__device__ float         g_w2t[512 * 256];               // [k][c]: c<128 pri_W2, else pos_W2

enum : int {
    OFF_encW0  = 0,
    OFF_encW1  = OFF_encW0  + 512 * 256,
    OFF_encW2  = OFF_encW1  + 512 * 512,
    OFF_posW0e = OFF_encW2  + 512 * 512,
    OFF_posW0h = OFF_posW0e + 512 * 512,
    OFF_priW0  = OFF_posW0h + 512 * 512,
    OFF_gruWhh = OFF_priW0  + 512 * 512,
    OFF_priW1  = OFF_gruWhh + 1536 * 512,
    OFF_posW1  = OFF_priW1  + 512 * 512,
    OFF_priW2  = OFF_posW1  + 512 * 512,
    OFF_posW2  = OFF_priW2  + 128 * 512,
    OFF_decW0  = OFF_posW2  + 128 * 512,
    OFF_decW1  = OFF_decW0  + 512 * 64,
    OFF_decW2  = OFF_decW1  + 512 * 512,
    WTOT       = OFF_decW2  + 256 * 512
};
__device__ __nv_bfloat16 g_whi[WTOT];
__device__ __nv_bfloat16 g_wlo[WTOT];

__device__ __forceinline__ float eluf(float x) { return x > 0.f ? x : expm1f(x); }

__device__ __forceinline__ uint32_t smem_u32(const void* p) {
    uint32_t a;
    asm("{ .reg .u64 t; cvta.to.shared.u64 t, %1; cvt.u32.u64 %0, t; }" : "=r"(a) : "l"(p));
    return a;
}
__device__ __forceinline__ void cpasync16(uint32_t saddr, const void* gptr) {
    asm volatile("cp.async.cg.shared.global [%0], [%1], 16;" :: "r"(saddr), "l"(gptr));
}
__device__ __forceinline__ void cp_commit() {
    asm volatile("cp.async.commit_group;" ::: "memory");
}
__device__ __forceinline__ void ldsm4(uint32_t* r, uint32_t addr) {
    asm volatile("ldmatrix.sync.aligned.m8n8.x4.shared.b16 {%0,%1,%2,%3}, [%4];"
                 : "=r"(r[0]), "=r"(r[1]), "=r"(r[2]), "=r"(r[3]) : "r"(addr));
}
__device__ __forceinline__ void mma_bf16(float* c, const uint32_t* a, uint32_t b0, uint32_t b1) {
    asm volatile(
        "mma.sync.aligned.m16n8k16.row.col.f32.bf16.bf16.f32 "
        "{%0,%1,%2,%3}, {%4,%5,%6,%7}, {%8,%9}, {%0,%1,%2,%3};"
        : "+f"(c[0]), "+f"(c[1]), "+f"(c[2]), "+f"(c[3])
        : "r"(a[0]), "r"(a[1]), "r"(a[2]), "r"(a[3]), "r"(b0), "r"(b1));
}

// ---------------------------------------------------------------------------
// Grouped GEMM descriptor (up to 3 groups; tiles never straddle groups)
// AMODE: 0 = A fp32 (register prefetch), 1 = A bf16 pairs (cp.async),
//        2 = A = elu(Af + Af2) fp32 partial-sum (inline load)
// ksplit: K split factor (blockIdx.z). Partials written at Cf + z*csplit.
// ---------------------------------------------------------------------------
struct GemmTC {
    const float*         Af[3];
    const float*         Af2[3];
    const __nv_bfloat16* Ahi[3];
    const __nv_bfloat16* Alo[3];
    int                  lda[3];
    const __nv_bfloat16* Whi[3];
    const __nv_bfloat16* Wlo[3];
    const float*         bias[3];
    const float*         add[3];
    long                 ldadd[3];
    float*               Cf[3];
    __nv_bfloat16*       Chi[3];
    __nv_bfloat16*       Clo[3];
    int                  ldc[3];
    int                  act[3];
    int                  mode[3];   // 0 = fp32 out, 1 = bf16 pairs out
    int                  n_off[4];
    int K, ng, ksplit;
    long csplit;
};

template <int AMODE>
__global__ void __launch_bounds__(256, 2) gemm_tc(GemmTC d) {
    extern __shared__ char smem[];
    const uint32_t sb = smem_u32(smem);

    const int tid = threadIdx.x;
    const int wid = tid >> 5;
    const int lane = tid & 31;
    const int warp_m = wid & 1;
    const int warp_n = wid >> 1;

    const int n0 = blockIdx.x * 128;
    const int m0 = blockIdx.y * 128;
    int g = 0;
    while (g + 1 < d.ng && n0 >= d.n_off[g + 1]) g++;
    const int nl0 = n0 - d.n_off[g];
    const int ldw = d.K;
    const int kz = (d.ksplit > 1) ? (int)blockIdx.z : 0;
    const int Ks = d.K / d.ksplit;
    const int kbase = kz * Ks;
    const int NC = Ks >> 5;

    const float*         Af  = (AMODE != 1) ? d.Af[g] + kbase : nullptr;
    const float*         Af2 = (AMODE == 2) ? d.Af2[g] + kbase : nullptr;
    const __nv_bfloat16* Ahi = (AMODE == 1) ? d.Ahi[g] + kbase : nullptr;
    const __nv_bfloat16* Alo = (AMODE == 1) ? d.Alo[g] + kbase : nullptr;
    const int lda = d.lda[g];
    const __nv_bfloat16* Whi = d.Whi[g] + (size_t)nl0 * ldw + kbase;
    const __nv_bfloat16* Wlo = d.Wlo[g] + (size_t)nl0 * ldw + kbase;

    float acc[4][4][4];
#pragma unroll
    for (int i = 0; i < 4; i++)
#pragma unroll
        for (int j = 0; j < 4; j++)
#pragma unroll
            for (int q = 0; q < 4; q++) acc[i][j][q] = 0.f;

    // ---- async issue helpers (256 threads) ----
    auto issueW = [&](int kc) {
        const uint32_t st = sb + (kc & 1) * STG;
        const int k0 = kc << 5;
#pragma unroll
        for (int i = 0; i < 2; i++) {
            const int idx = tid + i * 256;
            const int row = idx >> 2, ch = idx & 3;
            const uint32_t so = st + 20480 + row * 80 + ch * 16;
            cpasync16(so,         Whi + (size_t)row * ldw + k0 + ch * 8);
            cpasync16(so + 10240, Wlo + (size_t)row * ldw + k0 + ch * 8);
        }
    };
    auto issueA_pairs = [&](int kc) {
        const uint32_t st = sb + (kc & 1) * STG;
        const int k0 = kc << 5;
#pragma unroll
        for (int i = 0; i < 2; i++) {
            const int idx = tid + i * 256;
            const int row = idx >> 2, ch = idx & 3;
            const uint32_t so = st + row * 80 + ch * 16;
            cpasync16(so,         Ahi + (size_t)(m0 + row) * lda + k0 + ch * 8);
            cpasync16(so + 10240, Alo + (size_t)(m0 + row) * lda + k0 + ch * 8);
        }
    };

    auto cvt_store = [&](char* stp, int row, int col,
                         float x0, float x1, float x2, float x3) {
        __nv_bfloat162 h01 = __floats2bfloat162_rn(x0, x1);
        __nv_bfloat162 h23 = __floats2bfloat162_rn(x2, x3);
        __nv_bfloat162 l01 = __floats2bfloat162_rn(x0 - __bfloat162float(h01.x),
                                                   x1 - __bfloat162float(h01.y));
        __nv_bfloat162 l23 = __floats2bfloat162_rn(x2 - __bfloat162float(h23.x),
                                                   x3 - __bfloat162float(h23.y));
        const int bo = row * 80 + col * 2;
        *reinterpret_cast<uint2*>(stp + bo) =
            make_uint2(*reinterpret_cast<uint32_t*>(&h01), *reinterpret_cast<uint32_t*>(&h23));
        *reinterpret_cast<uint2*>(stp + 10240 + bo) =
            make_uint2(*reinterpret_cast<uint32_t*>(&l01), *reinterpret_cast<uint32_t*>(&l23));
    };

    float av[16];
    auto ldgA = [&](int kc) {
        const int k0 = kc << 5;
#pragma unroll
        for (int i = 0; i < 4; i++) {
            const int idx = tid + i * 256;
            const int row = idx >> 3, col = (idx & 7) * 4;
            const float4 v = *reinterpret_cast<const float4*>(
                Af + (size_t)(m0 + row) * lda + k0 + col);
            av[i * 4 + 0] = v.x; av[i * 4 + 1] = v.y;
            av[i * 4 + 2] = v.z; av[i * 4 + 3] = v.w;
        }
    };
    auto storeA = [&](int kc) {
        char* stp = smem + (kc & 1) * STG;
#pragma unroll
        for (int i = 0; i < 4; i++) {
            const int idx = tid + i * 256;
            const int row = idx >> 3, col = (idx & 7) * 4;
            cvt_store(stp, row, col, av[i * 4 + 0], av[i * 4 + 1], av[i * 4 + 2], av[i * 4 + 3]);
        }
    };
    auto storeA2 = [&](int kc) {   // inline: elu(Af + Af2) -> pairs
        char* stp = smem + (kc & 1) * STG;
        const int k0 = kc << 5;
#pragma unroll
        for (int i = 0; i < 4; i++) {
            const int idx = tid + i * 256;
            const int row = idx >> 3, col = (idx & 7) * 4;
            const size_t go = (size_t)(m0 + row) * lda + k0 + col;
            const float4 v0 = *reinterpret_cast<const float4*>(Af + go);
            const float4 v1 = *reinterpret_cast<const float4*>(Af2 + go);
            cvt_store(stp, row, col,
                      eluf(v0.x + v1.x), eluf(v0.y + v1.y),
                      eluf(v0.z + v1.z), eluf(v0.w + v1.w));
        }
    };

    // ---- fragment address bases ----
    const int lane15 = lane & 15;
    const int koff = (lane >> 4) << 3;
    const uint32_t arow = (uint32_t)(warp_m * 64 + lane15);
    const uint32_t brow = (uint32_t)(warp_n * 32 + lane15);

    // Interleaved sweeps: same-accumulator MMAs are 8 apart (j x mf sweep).
    auto compute = [&](int kc) {
        const uint32_t stb = sb + (kc & 1) * STG;
#pragma unroll
        for (int ks = 0; ks < 32; ks += 16) {
            const uint32_t acol = (uint32_t)(ks + koff) * 2;
            uint32_t ah[4][4], al[4][4];
#pragma unroll
            for (int mf = 0; mf < 4; mf++) {
                const uint32_t ad = stb + (arow + mf * 16) * 80 + acol;
                ldsm4(ah[mf], ad);
                ldsm4(al[mf], ad + 10240);
            }
#pragma unroll
            for (int nfp = 0; nfp < 2; nfp++) {
                const uint32_t bd = stb + 20480 + (brow + nfp * 16) * 80 + acol;
                uint32_t bh[4], bl[4];
                ldsm4(bh, bd);
                ldsm4(bl, bd + 10240);
                // sweep 1: ah x bh over (j, mf) — 8 MMAs, distance 8 per acc
#pragma unroll
                for (int j = 0; j < 2; j++)
#pragma unroll
                    for (int mf = 0; mf < 4; mf++)
                        mma_bf16(acc[mf][nfp * 2 + j], ah[mf], bh[j], bh[2 + j]);
                // sweep 2: ah x bl
#pragma unroll
                for (int j = 0; j < 2; j++)
#pragma unroll
                    for (int mf = 0; mf < 4; mf++)
                        mma_bf16(acc[mf][nfp * 2 + j], ah[mf], bl[j], bl[2 + j]);
                // sweep 3: al x bh
#pragma unroll
                for (int j = 0; j < 2; j++)
#pragma unroll
                    for (int mf = 0; mf < 4; mf++)
                        mma_bf16(acc[mf][nfp * 2 + j], al[mf], bh[j], bh[2 + j]);
            }
        }
    };

    // ---- pipeline ----
    if (AMODE == 1) {
        issueA_pairs(0); issueW(0); cp_commit();
        for (int kc = 0; kc < NC; kc++) {
            if (kc + 1 < NC) { issueA_pairs(kc + 1); issueW(kc + 1); cp_commit(); }
            if (kc + 1 < NC) asm volatile("cp.async.wait_group 1;" ::: "memory");
            else             asm volatile("cp.async.wait_group 0;" ::: "memory");
            __syncthreads();
            compute(kc);
            __syncthreads();
        }
    } else if (AMODE == 0) {
        ldgA(0);
        issueW(0); cp_commit();
        for (int kc = 0; kc < NC; kc++) {
            storeA(kc);
            if (kc + 1 < NC) { issueW(kc + 1); cp_commit(); }
            if (kc + 1 < NC) asm volatile("cp.async.wait_group 1;" ::: "memory");
            else             asm volatile("cp.async.wait_group 0;" ::: "memory");
            __syncthreads();
            if (kc + 1 < NC) ldgA(kc + 1);
            compute(kc);
            __syncthreads();
        }
    } else {
        issueW(0); cp_commit();
        for (int kc = 0; kc < NC; kc++) {
            if (kc + 1 < NC) { issueW(kc + 1); cp_commit(); }
            storeA2(kc);
            if (kc + 1 < NC) asm volatile("cp.async.wait_group 1;" ::: "memory");
            else             asm volatile("cp.async.wait_group 0;" ::: "memory");
            __syncthreads();
            compute(kc);
            __syncthreads();
        }
    }

    // ---- epilogue ----
    const float* bias = (kz == 0) ? d.bias[g] : nullptr;
    const float* add  = (kz == 0) ? d.add[g] : nullptr;
    const long ldadd  = d.ldadd[g];
    const int act     = d.act[g];
    const int mode    = d.mode[g];
    const int ldc     = d.ldc[g];
    float* Cf         = d.Cf[g] + (size_t)kz * d.csplit;
    __nv_bfloat16* Chi = d.Chi[g];
    __nv_bfloat16* Clo = d.Clo[g];

    const int gid = lane >> 2;
    const int tig = lane & 3;
#pragma unroll
    for (int mf = 0; mf < 4; mf++) {
        const int r0 = m0 + warp_m * 64 + mf * 16 + gid;
#pragma unroll
        for (int nf = 0; nf < 4; nf++) {
            const int coll = nl0 + warp_n * 32 + nf * 8 + tig * 2;
            float v0 = acc[mf][nf][0], v1 = acc[mf][nf][1];
            float v2 = acc[mf][nf][2], v3 = acc[mf][nf][3];
            if (bias) {
                const float b0v = bias[coll], b1v = bias[coll + 1];
                v0 += b0v; v1 += b1v; v2 += b0v; v3 += b1v;
            }
            if (add) {
                const float2 a0 = *reinterpret_cast<const float2*>(add + (size_t)r0 * ldadd + coll);
                const float2 a1 = *reinterpret_cast<const float2*>(add + (size_t)(r0 + 8) * ldadd + coll);
                v0 += a0.x; v1 += a0.y; v2 += a1.x; v3 += a1.y;
            }
            if (act) { v0 = eluf(v0); v1 = eluf(v1); v2 = eluf(v2); v3 = eluf(v3); }
            if (mode == 0) {
                *reinterpret_cast<float2*>(Cf + (size_t)r0 * ldc + coll)       = make_float2(v0, v1);
                *reinterpret_cast<float2*>(Cf + (size_t)(r0 + 8) * ldc + coll) = make_float2(v2, v3);
            } else {
                __nv_bfloat162 h0 = __floats2bfloat162_rn(v0, v1);
                __nv_bfloat162 l0 = __floats2bfloat162_rn(v0 - __bfloat162float(h0.x),
                                                          v1 - __bfloat162float(h0.y));
                __nv_bfloat162 h1 = __floats2bfloat162_rn(v2, v3);
                __nv_bfloat162 l1 = __floats2bfloat162_rn(v2 - __bfloat162float(h1.x),
                                                          v3 - __bfloat162float(h1.y));
                *reinterpret_cast<uint32_t*>(Chi + (size_t)r0 * ldc + coll)       = *reinterpret_cast<uint32_t*>(&h0);
                *reinterpret_cast<uint32_t*>(Clo + (size_t)r0 * ldc + coll)       = *reinterpret_cast<uint32_t*>(&l0);
                *reinterpret_cast<uint32_t*>(Chi + (size_t)(r0 + 8) * ldc + coll) = *reinterpret_cast<uint32_t*>(&h1);
                *reinterpret_cast<uint32_t*>(Clo + (size_t)(r0 + 8) * ldc + coll) = *reinterpret_cast<uint32_t*>(&l1);
            }
        }
    }
}

// ---------------------------------------------------------------------------
// Single init kernel: pack all weights (hi/lo), Wih^T, W2^T, zero h
// ---------------------------------------------------------------------------
struct PackArgs {
    const float* src[14];
    int ld[14];
    int coff[14];
    const float* wih;
};
__constant__ int c_seg_off[15] = {
    OFF_encW0, OFF_encW1, OFF_encW2, OFF_posW0e, OFF_posW0h, OFF_priW0,
    OFF_gruWhh, OFF_priW1, OFF_posW1, OFF_priW2, OFF_posW2, OFF_decW0,
    OFF_decW1, OFF_decW2, WTOT
};
__constant__ int c_seg_K[14] = {
    256, 512, 512, 512, 512, 512, 512, 512, 512, 512, 512, 64, 512, 512
};

#define PACK_EXTRA (64 * 1536 + B_ * 512 + 512 * 256)
__global__ void pack_all(PackArgs a) {
    const int i = blockIdx.x * 256 + threadIdx.x;
    if (i < WTOT) {
        int s = 0;
        while (s + 1 < 14 && i >= c_seg_off[s + 1]) s++;
        const int li = i - c_seg_off[s];
        const int K = c_seg_K[s];
        const int r = li / K, k = li - r * K;
        const float v = a.src[s][(size_t)r * a.ld[s] + a.coff[s] + k];
        const __nv_bfloat16 h = __float2bfloat16(v);
        g_whi[i] = h;
        g_wlo[i] = __float2bfloat16(v - __bfloat162float(h));
    } else if (i < WTOT + 64 * 1536) {
        const int li = i - WTOT;
        const int row = li / 64, k = li - row * 64;
        g_wiht[k * 1536 + row] = a.wih[li];
    } else if (i < WTOT + 64 * 1536 + B_ * 512) {
        const int li = i - WTOT - 64 * 1536;
        g_h[li] = 0.f;
        g_h_hi[li] = __float2bfloat16(0.f);
        g_h_lo[li] = __float2bfloat16(0.f);
    } else if (i < WTOT + 64 * 1536 + B_ * 512 + 512 * 256) {
        const int li = i - WTOT - 64 * 1536 - B_ * 512;
        const int k = li >> 8, c = li & 255;
        g_w2t[li] = (c < 128) ? a.src[9][(size_t)c * 512 + k]
                              : a.src[10][(size_t)(c - 128) * 512 + k];
    }
}

// ---------------------------------------------------------------------------
// Fused S3 + latent + GRU kernel (per timestep).
// Sums 4 S2 partials (elu) for A; sums 2 gh partials in the gate phase.
// ---------------------------------------------------------------------------
#define TMB 8
#define A1_PB ((size_t)B_ * 1024)
#define S1_PB ((size_t)B_ * 2560)
__global__ void __launch_bounds__(512) s3_gru_kernel(
    const float* __restrict__ eps,
    const float* __restrict__ bih,
    const float* __restrict__ pri_b2,
    const float* __restrict__ pos_b2,
    float* __restrict__ kls_out,
    float* __restrict__ mu_out,
    int t)
{
    __shared__ __align__(16) float sA[TMB][1024];
    __shared__ float s_out2[TMB][256];
    __shared__ float zs[TMB][64];
    __shared__ float klw[TMB][2];

    const int m0 = blockIdx.x * TMB;
    const int tid = threadIdx.x;   // 512 threads

    // ---- Phase 1: sA = elu(sum of 4 S2 partials) ----
    {
#pragma unroll
        for (int i = 0; i < 4; i++) {
            const int idx = tid + i * 512;
            const int row = idx >> 8, c4 = (idx & 255) * 4;
            const size_t go = (size_t)(m0 + row) * 1024 + c4;
            const float4 v0 = *reinterpret_cast<const float4*>(g_a1p + go);
            const float4 v1 = *reinterpret_cast<const float4*>(g_a1p + A1_PB + go);
            const float4 v2 = *reinterpret_cast<const float4*>(g_a1p + 2 * A1_PB + go);
            const float4 v3 = *reinterpret_cast<const float4*>(g_a1p + 3 * A1_PB + go);
            sA[row][c4 + 0] = eluf(v0.x + v1.x + v2.x + v3.x);
            sA[row][c4 + 1] = eluf(v0.y + v1.y + v2.y + v3.y);
            sA[row][c4 + 2] = eluf(v0.z + v1.z + v2.z + v3.z);
            sA[row][c4 + 3] = eluf(v0.w + v1.w + v2.w + v3.w);
        }
    }
    __syncthreads();

    // ---- Phase 2: out2[r][c] = sum_k A[r][aoff+k] * W2t[k][c]  (split-k x2) ----
    {
        const int c = tid & 255;
        const int kh = tid >> 8;
        const int aoff = ((c < 128) ? 0 : 512) + kh * 256;
        const float* wp = g_w2t + (size_t)(kh * 256) * 256 + c;
        float accs[TMB];
#pragma unroll
        for (int r = 0; r < TMB; r++) accs[r] = 0.f;
#pragma unroll 4
        for (int kk = 0; kk < 64; kk++) {
            const float w0 = wp[(kk * 4 + 0) * 256];
            const float w1 = wp[(kk * 4 + 1) * 256];
            const float w2 = wp[(kk * 4 + 2) * 256];
            const float w3 = wp[(kk * 4 + 3) * 256];
#pragma unroll
            for (int r = 0; r < TMB; r++) {
                const float4 av = *reinterpret_cast<const float4*>(&sA[r][aoff + kk * 4]);
                accs[r] = fmaf(av.x, w0, fmaf(av.y, w1, fmaf(av.z, w2, fmaf(av.w, w3, accs[r]))));
            }
        }
        if (kh == 1) {
#pragma unroll
            for (int r = 0; r < TMB; r++) s_out2[r][c] = accs[r];
        }
        __syncthreads();
        if (kh == 0) {
            const float b = (c < 128) ? pri_b2[c] : pos_b2[c - 128];
#pragma unroll
            for (int r = 0; r < TMB; r++) s_out2[r][c] = accs[r] + s_out2[r][c] + b;
        }
        __syncthreads();
    }

    // ---- Phase 3: latent sample + KL + mu ----
    {
        const int r = tid >> 6, k = tid & 63;
        const int m = m0 + r;
        const float mu_p = s_out2[r][k];
        const float ls_p = s_out2[r][64 + k];
        const float mu_q = s_out2[r][128 + k];
        const float ls_q = s_out2[r][192 + k];
        const float e = eps[((size_t)m * T_ + t) * 64 + k];
        const float zl = fmaf(expf(ls_q), e, mu_q);
        zs[r][k] = zl;
        const __nv_bfloat16 zh = __float2bfloat16(zl);
        g_z_hi[((size_t)m * T_ + t) * 64 + k] = zh;
        g_z_lo[((size_t)m * T_ + t) * 64 + k] = __float2bfloat16(zl - __bfloat162float(zh));
        mu_out[((size_t)m * T_ + t) * 64 + k] = mu_q;
        const float dm = mu_q - mu_p;
        float klv = ls_p - ls_q + (expf(2.f * ls_q) + dm * dm) / (2.f * expf(2.f * ls_p)) - 0.5f;
#pragma unroll
        for (int off = 16; off > 0; off >>= 1)
            klv += __shfl_down_sync(0xffffffffu, klv, off);
        if ((tid & 31) == 0) klw[r][(tid >> 5) & 1] = klv;
    }
    __syncthreads();
    if (tid < TMB) kls_out[(size_t)(m0 + tid) * T_ + t] = klw[tid][0] + klw[tid][1];

    // ---- Phase 4: GRU gates + h update (gh = sum of 2 partials) ----
    {
        const int j = tid;
        float ar[TMB], az[TMB], an[TMB];
#pragma unroll
        for (int r = 0; r < TMB; r++) { ar[r] = 0.f; az[r] = 0.f; an[r] = 0.f; }

#pragma unroll 4
        for (int k = 0; k < 64; k++) {
            const float wr = g_wiht[k * 1536 + j];
            const float wz = g_wiht[k * 1536 + 512 + j];
            const float wn = g_wiht[k * 1536 + 1024 + j];
#pragma unroll
            for (int r = 0; r < TMB; r++) {
                const float zk = zs[r][k];
                ar[r] = fmaf(zk, wr, ar[r]);
                az[r] = fmaf(zk, wz, az[r]);
                an[r] = fmaf(zk, wn, an[r]);
            }
        }

        const float br = bih[j], bz = bih[512 + j], bn = bih[1024 + j];
#pragma unroll
        for (int r = 0; r < TMB; r++) {
            const int m = m0 + r;
            const float* g0 = g_s1p + (size_t)m * 2560 + 1024;
            const float ghr = g0[j]        + g0[S1_PB + j];
            const float ghz = g0[512 + j]  + g0[S1_PB + 512 + j];
            const float ghn = g0[1024 + j] + g0[S1_PB + 1024 + j];
            const float rg = 1.f / (1.f + expf(-(ar[r] + br + ghr)));
            const float zg = 1.f / (1.f + expf(-(az[r] + bz + ghz)));
            const float ng = tanhf(an[r] + bn + rg * ghn);
            const float hv = g_h[(size_t)m * 512 + j];
            const float hn = (1.f - zg) * ng + zg * hv;
            g_h[(size_t)m * 512 + j] = hn;
            const __nv_bfloat16 hh = __float2bfloat16(hn);
            g_h_hi[(size_t)m * 512 + j] = hh;
            g_h_lo[(size_t)m * 512 + j] = __float2bfloat16(hn - __bfloat162float(hh));
        }
    }
}

// ---------------------------------------------------------------------------
// Host helpers
// ---------------------------------------------------------------------------
static inline GemmTC make_desc(int K, int ksplit = 1, long csplit = 0) {
    GemmTC d{};
    d.K = K; d.ng = 0; d.n_off[0] = 0;
    d.ksplit = ksplit; d.csplit = csplit;
    return d;
}
static inline void add_group(GemmTC& d, int nsub,
                             const float* Af, const float* Af2,
                             const __nv_bfloat16* Ahi, const __nv_bfloat16* Alo, int lda,
                             const __nv_bfloat16* Whi, const __nv_bfloat16* Wlo,
                             const float* bias, const float* add, long ldadd, int act,
                             int mode, float* Cf, __nv_bfloat16* Chi, __nv_bfloat16* Clo, int ldc) {
    const int g = d.ng;
    d.Af[g] = Af; d.Af2[g] = Af2; d.Ahi[g] = Ahi; d.Alo[g] = Alo; d.lda[g] = lda;
    d.Whi[g] = Whi; d.Wlo[g] = Wlo;
    d.bias[g] = bias; d.add[g] = add; d.ldadd[g] = ldadd;
    d.act[g] = act; d.mode[g] = mode;
    d.Cf[g] = Cf; d.Chi[g] = Chi; d.Clo[g] = Clo; d.ldc[g] = ldc;
    d.n_off[g + 1] = d.n_off[g] + nsub;
    d.ng = g + 1;
}

extern "C" void kernel_launch(void* const* d_in, const int* in_sizes, int n_in,
                              void* d_out, int out_size) {
    const float* obs     = (const float*)d_in[0];
    const float* eps     = (const float*)d_in[1];
    const float* enc_W0  = (const float*)d_in[2];
    const float* enc_b0  = (const float*)d_in[3];
    const float* enc_W1  = (const float*)d_in[4];
    const float* enc_b1  = (const float*)d_in[5];
    const float* enc_W2  = (const float*)d_in[6];
    const float* enc_b2  = (const float*)d_in[7];
    const float* pri_W0  = (const float*)d_in[8];
    const float* pri_b0  = (const float*)d_in[9];
    const float* pri_W1  = (const float*)d_in[10];
    const float* pri_b1  = (const float*)d_in[11];
    const float* pri_W2  = (const float*)d_in[12];
    const float* pri_b2  = (const float*)d_in[13];
    const float* pos_W0  = (const float*)d_in[14];
    const float* pos_b0  = (const float*)d_in[15];
    const float* pos_W1  = (const float*)d_in[16];
    const float* pos_b1  = (const float*)d_in[17];
    const float* pos_W2  = (const float*)d_in[18];
    const float* pos_b2  = (const float*)d_in[19];
    const float* dec_W0  = (const float*)d_in[20];
    const float* dec_b0  = (const float*)d_in[21];
    const float* dec_W1  = (const float*)d_in[22];
    const float* dec_b1  = (const float*)d_in[23];
    const float* dec_W2  = (const float*)d_in[24];
    const float* dec_b2  = (const float*)d_in[25];
    const float* gru_Wih = (const float*)d_in[26];
    const float* gru_bih = (const float*)d_in[27];
    const float* gru_Whh = (const float*)d_in[28];
    const float* gru_bhh = (const float*)d_in[29];
    (void)in_sizes; (void)n_in; (void)out_size;

    __nv_bfloat16 *bufA_hi, *bufA_lo, *bufB_hi, *bufB_lo, *z_hi, *z_lo;
    __nv_bfloat16 *whi, *wlo, *h_hi, *h_lo;
    float *posc, *s1p, *a1p;
    cudaGetSymbolAddress((void**)&bufA_hi, g_bufA_hi);
    cudaGetSymbolAddress((void**)&bufA_lo, g_bufA_lo);
    cudaGetSymbolAddress((void**)&bufB_hi, g_bufB_hi);
    cudaGetSymbolAddress((void**)&bufB_lo, g_bufB_lo);
    cudaGetSymbolAddress((void**)&z_hi,    g_z_hi);
    cudaGetSymbolAddress((void**)&z_lo,    g_z_lo);
    cudaGetSymbolAddress((void**)&posc,    g_posc);
    cudaGetSymbolAddress((void**)&whi,     g_whi);
    cudaGetSymbolAddress((void**)&wlo,     g_wlo);
    cudaGetSymbolAddress((void**)&s1p,     g_s1p);
    cudaGetSymbolAddress((void**)&a1p,     g_a1p);
    cudaGetSymbolAddress((void**)&h_hi,    g_h_hi);
    cudaGetSymbolAddress((void**)&h_lo,    g_h_lo);

    cudaFuncSetAttribute(gemm_tc<0>, cudaFuncAttributeMaxDynamicSharedMemorySize, SMEM_DYN);
    cudaFuncSetAttribute(gemm_tc<1>, cudaFuncAttributeMaxDynamicSharedMemorySize, SMEM_DYN);
    cudaFuncSetAttribute(gemm_tc<2>, cudaFuncAttributeMaxDynamicSharedMemorySize, SMEM_DYN);

    float* recons = (float*)d_out;
    float* kls    = recons + (size_t)BT_ * OBS_;
    float* mu     = kls + BT_;

    // ---- single init/pack launch ----
    PackArgs pa;
    const float* srcs[14] = { enc_W0, enc_W1, enc_W2, pos_W0, pos_W0, pri_W0, gru_Whh,
                              pri_W1, pos_W1, pri_W2, pos_W2, dec_W0, dec_W1, dec_W2 };
    const int lds[14]   = { 256, 512, 512, 1024, 1024, 512, 512, 512, 512, 512, 512, 64, 512, 512 };
    const int coffs[14] = { 0, 0, 0, 512, 0, 0, 0, 0, 0, 0, 0, 0, 0, 0 };
    for (int i = 0; i < 14; i++) { pa.src[i] = srcs[i]; pa.ld[i] = lds[i]; pa.coff[i] = coffs[i]; }
    pa.wih = gru_Wih;
    pack_all<<<(WTOT + PACK_EXTRA + 255) / 256, 256>>>(pa);

    // ---- Encoder chain (parallel over B*T) ----
    {
        GemmTC d = make_desc(256);
        add_group(d, 512, obs, nullptr, nullptr, nullptr, 256, whi + OFF_encW0, wlo + OFF_encW0,
                  enc_b0, nullptr, 0, 1, 1, nullptr, bufA_hi, bufA_lo, 512);
        gemm_tc<0><<<dim3(4, BT_ / 128), 256, SMEM_DYN>>>(d);
    }
    {
        GemmTC d = make_desc(512);
        add_group(d, 512, nullptr, nullptr, bufA_hi, bufA_lo, 512, whi + OFF_encW1, wlo + OFF_encW1,
                  enc_b1, nullptr, 0, 1, 1, nullptr, bufB_hi, bufB_lo, 512);
        gemm_tc<1><<<dim3(4, BT_ / 128), 256, SMEM_DYN>>>(d);
    }
    {
        GemmTC d = make_desc(512);
        add_group(d, 512, nullptr, nullptr, bufB_hi, bufB_lo, 512, whi + OFF_encW2, wlo + OFF_encW2,
                  enc_b2, nullptr, 0, 0, 1, nullptr, bufA_hi, bufA_lo, 512);
        gemm_tc<1><<<dim3(4, BT_ / 128), 256, SMEM_DYN>>>(d);
    }
    {
        GemmTC d = make_desc(512);
        add_group(d, 512, nullptr, nullptr, bufA_hi, bufA_lo, 512, whi + OFF_posW0e, wlo + OFF_posW0e,
                  pos_b0, nullptr, 0, 0, 0, posc, nullptr, nullptr, 512);
        gemm_tc<1><<<dim3(4, BT_ / 128), 256, SMEM_DYN>>>(d);
    }

    // ---- Sequential recurrence (3 launches per step, R11 shapes) ----
    for (int t = 0; t < T_; t++) {
        // S1: h -> [pri_a0 | pos_a0 | gh] fp32 partials, split-K x2
        {
            GemmTC d = make_desc(512, 2, (long)B_ * 2560);
            add_group(d, 512, nullptr, nullptr, h_hi, h_lo, 512, whi + OFF_priW0, wlo + OFF_priW0,
                      pri_b0, nullptr, 0, 0, 0, s1p, nullptr, nullptr, 2560);
            add_group(d, 512, nullptr, nullptr, h_hi, h_lo, 512, whi + OFF_posW0h, wlo + OFF_posW0h,
                      nullptr, posc + (size_t)t * 512, (long)T_ * 512, 0,
                      0, s1p + 512, nullptr, nullptr, 2560);
            add_group(d, 1536, nullptr, nullptr, h_hi, h_lo, 512, whi + OFF_gruWhh, wlo + OFF_gruWhh,
                      gru_bhh, nullptr, 0, 0, 0, s1p + 1024, nullptr, nullptr, 2560);
            gemm_tc<1><<<dim3(20, 8, 2), 256, SMEM_DYN>>>(d);
        }
        // S2: A = elu(s1p0 + s1p1), fp32 partials out, split-K x4
        {
            GemmTC d = make_desc(512, 4, (long)B_ * 1024);
            add_group(d, 512, s1p, s1p + (size_t)B_ * 2560, nullptr, nullptr, 2560,
                      whi + OFF_priW1, wlo + OFF_priW1,
                      pri_b1, nullptr, 0, 0, 0, a1p, nullptr, nullptr, 1024);
            add_group(d, 512, s1p + 512, s1p + (size_t)B_ * 2560 + 512, nullptr, nullptr, 2560,
                      whi + OFF_posW1, wlo + OFF_posW1,
                      pos_b1, nullptr, 0, 0, 0, a1p + 512, nullptr, nullptr, 1024);
            gemm_tc<2><<<dim3(8, 8, 4), 256, SMEM_DYN>>>(d);
        }
        // S3 + latent + GRU fused
        s3_gru_kernel<<<B_ / TMB, 512>>>(eps, gru_bih, pri_b2, pos_b2, kls, mu, t);
    }

    // ---- Deferred decoder over all (B*T) rows ----
    {
        GemmTC d = make_desc(64);
        add_group(d, 512, nullptr, nullptr, z_hi, z_lo, 64, whi + OFF_decW0, wlo + OFF_decW0,
                  dec_b0, nullptr, 0, 1, 1, nullptr, bufA_hi, bufA_lo, 512);
        gemm_tc<1><<<dim3(4, BT_ / 128), 256, SMEM_DYN>>>(d);
    }
    {
        GemmTC d = make_desc(512);
        add_group(d, 512, nullptr, nullptr, bufA_hi, bufA_lo, 512, whi + OFF_decW1, wlo + OFF_decW1,
                  dec_b1, nullptr, 0, 1, 1, nullptr, bufB_hi, bufB_lo, 512);
        gemm_tc<1><<<dim3(4, BT_ / 128), 256, SMEM_DYN>>>(d);
    }
    {
        GemmTC d = make_desc(512);
        add_group(d, 256, nullptr, nullptr, bufB_hi, bufB_lo, 512, whi + OFF_decW2, wlo + OFF_decW2,
                  dec_b2, nullptr, 0, 0, 0, recons, nullptr, nullptr, 256);
        gemm_tc<1><<<dim3(2, BT_ / 128), 256, SMEM_DYN>>>(d);
    }
}

// round 17
// speedup vs baseline: 1.2524x; 1.0151x over previous
#include <cuda_runtime.h>
#include <cuda_bf16.h>
#include <cstdint>

// Problem constants
#define B_   1024
#define T_   128
#define OBS_ 256
#define LAT_ 64
#define BT_  (B_ * T_)   // 131072
#define STG  40960       // bytes per smem stage (4 arrays x 128 rows x 80B)
#define SMEM_DYN (2 * STG)

// ---------------------------------------------------------------------------
// Static device scratch
// ---------------------------------------------------------------------------
__device__ __nv_bfloat16 g_bufA_hi[(size_t)BT_ * 512];
__device__ __nv_bfloat16 g_bufA_lo[(size_t)BT_ * 512];
__device__ __nv_bfloat16 g_bufB_hi[(size_t)BT_ * 512];
__device__ __nv_bfloat16 g_bufB_lo[(size_t)BT_ * 512];
__device__ float         g_posc[(size_t)BT_ * 512];
__device__ __nv_bfloat16 g_z_hi[(size_t)BT_ * 64];
__device__ __nv_bfloat16 g_z_lo[(size_t)BT_ * 64];
__device__ float         g_s1p[2 * (size_t)B_ * 2560];   // S1 split-K partials: [pri|pos|gh]
__device__ float         g_a1p[4 * (size_t)B_ * 1024];   // S2 split-K partials
__device__ float         g_h[(size_t)B_ * 512];
__device__ __nv_bfloat16 g_h_hi[(size_t)B_ * 512];
__device__ __nv_bfloat16 g_h_lo[(size_t)B_ * 512];
__device__ float         g_wiht[64 * 1536];
__device__ float         g_w2t[512 * 256];               // [k][c]: c<128 pri_W2, else pos_W2

enum : int {
    OFF_encW0  = 0,
    OFF_encW1  = OFF_encW0  + 512 * 256,
    OFF_encW2  = OFF_encW1  + 512 * 512,
    OFF_posW0e = OFF_encW2  + 512 * 512,
    OFF_posW0h = OFF_posW0e + 512 * 512,
    OFF_priW0  = OFF_posW0h + 512 * 512,
    OFF_gruWhh = OFF_priW0  + 512 * 512,
    OFF_priW1  = OFF_gruWhh + 1536 * 512,
    OFF_posW1  = OFF_priW1  + 512 * 512,
    OFF_priW2  = OFF_posW1  + 512 * 512,
    OFF_posW2  = OFF_priW2  + 128 * 512,
    OFF_decW0  = OFF_posW2  + 128 * 512,
    OFF_decW1  = OFF_decW0  + 512 * 64,
    OFF_decW2  = OFF_decW1  + 512 * 512,
    WTOT       = OFF_decW2  + 256 * 512
};
__device__ __nv_bfloat16 g_whi[WTOT];
__device__ __nv_bfloat16 g_wlo[WTOT];

__device__ __forceinline__ float eluf(float x) { return x > 0.f ? x : expm1f(x); }

__device__ __forceinline__ void grid_dep_sync() {
#if defined(__CUDA_ARCH__) && (__CUDA_ARCH__ >= 900)
    cudaGridDependencySynchronize();
#endif
}

__device__ __forceinline__ uint32_t smem_u32(const void* p) {
    uint32_t a;
    asm("{ .reg .u64 t; cvta.to.shared.u64 t, %1; cvt.u32.u64 %0, t; }" : "=r"(a) : "l"(p));
    return a;
}
__device__ __forceinline__ void cpasync16(uint32_t saddr, const void* gptr) {
    asm volatile("cp.async.cg.shared.global [%0], [%1], 16;" :: "r"(saddr), "l"(gptr));
}
__device__ __forceinline__ void cp_commit() {
    asm volatile("cp.async.commit_group;" ::: "memory");
}
__device__ __forceinline__ void ldsm4(uint32_t* r, uint32_t addr) {
    asm volatile("ldmatrix.sync.aligned.m8n8.x4.shared.b16 {%0,%1,%2,%3}, [%4];"
                 : "=r"(r[0]), "=r"(r[1]), "=r"(r[2]), "=r"(r[3]) : "r"(addr));
}
__device__ __forceinline__ void mma_bf16(float* c, const uint32_t* a, uint32_t b0, uint32_t b1) {
    asm volatile(
        "mma.sync.aligned.m16n8k16.row.col.f32.bf16.bf16.f32 "
        "{%0,%1,%2,%3}, {%4,%5,%6,%7}, {%8,%9}, {%0,%1,%2,%3};"
        : "+f"(c[0]), "+f"(c[1]), "+f"(c[2]), "+f"(c[3])
        : "r"(a[0]), "r"(a[1]), "r"(a[2]), "r"(a[3]), "r"(b0), "r"(b1));
}

// ---------------------------------------------------------------------------
// Grouped GEMM descriptor (up to 3 groups; tiles never straddle groups)
// AMODE: 0 = A fp32 (register prefetch), 1 = A bf16 pairs (cp.async),
//        2 = A = elu(Af + Af2) fp32 partial-sum (inline load)
// ksplit: K split factor (blockIdx.z). Partials written at Cf + z*csplit.
// pdl: grid-dependency sync after chunk-0 weight issue (PDL overlap).
// ---------------------------------------------------------------------------
struct GemmTC {
    const float*         Af[3];
    const float*         Af2[3];
    const __nv_bfloat16* Ahi[3];
    const __nv_bfloat16* Alo[3];
    int                  lda[3];
    const __nv_bfloat16* Whi[3];
    const __nv_bfloat16* Wlo[3];
    const float*         bias[3];
    const float*         add[3];
    long                 ldadd[3];
    float*               Cf[3];
    __nv_bfloat16*       Chi[3];
    __nv_bfloat16*       Clo[3];
    int                  ldc[3];
    int                  act[3];
    int                  mode[3];   // 0 = fp32 out, 1 = bf16 pairs out
    int                  n_off[4];
    int K, ng, ksplit, pdl;
    long csplit;
};

template <int AMODE>
__global__ void __launch_bounds__(256, 2) gemm_tc(GemmTC d) {
    extern __shared__ char smem[];
    const uint32_t sb = smem_u32(smem);

    const int tid = threadIdx.x;
    const int wid = tid >> 5;
    const int lane = tid & 31;
    const int warp_m = wid & 1;
    const int warp_n = wid >> 1;

    const int n0 = blockIdx.x * 128;
    const int m0 = blockIdx.y * 128;
    int g = 0;
    while (g + 1 < d.ng && n0 >= d.n_off[g + 1]) g++;
    const int nl0 = n0 - d.n_off[g];
    const int ldw = d.K;
    const int kz = (d.ksplit > 1) ? (int)blockIdx.z : 0;
    const int Ks = d.K / d.ksplit;
    const int kbase = kz * Ks;
    const int NC = Ks >> 5;

    const float*         Af  = (AMODE != 1) ? d.Af[g] + kbase : nullptr;
    const float*         Af2 = (AMODE == 2) ? d.Af2[g] + kbase : nullptr;
    const __nv_bfloat16* Ahi = (AMODE == 1) ? d.Ahi[g] + kbase : nullptr;
    const __nv_bfloat16* Alo = (AMODE == 1) ? d.Alo[g] + kbase : nullptr;
    const int lda = d.lda[g];
    const __nv_bfloat16* Whi = d.Whi[g] + (size_t)nl0 * ldw + kbase;
    const __nv_bfloat16* Wlo = d.Wlo[g] + (size_t)nl0 * ldw + kbase;

    float acc[4][4][4];
#pragma unroll
    for (int i = 0; i < 4; i++)
#pragma unroll
        for (int j = 0; j < 4; j++)
#pragma unroll
            for (int q = 0; q < 4; q++) acc[i][j][q] = 0.f;

    // ---- async issue helpers (256 threads) ----
    auto issueW = [&](int kc) {
        const uint32_t st = sb + (kc & 1) * STG;
        const int k0 = kc << 5;
#pragma unroll
        for (int i = 0; i < 2; i++) {
            const int idx = tid + i * 256;
            const int row = idx >> 2, ch = idx & 3;
            const uint32_t so = st + 20480 + row * 80 + ch * 16;
            cpasync16(so,         Whi + (size_t)row * ldw + k0 + ch * 8);
            cpasync16(so + 10240, Wlo + (size_t)row * ldw + k0 + ch * 8);
        }
    };
    auto issueA_pairs = [&](int kc) {
        const uint32_t st = sb + (kc & 1) * STG;
        const int k0 = kc << 5;
#pragma unroll
        for (int i = 0; i < 2; i++) {
            const int idx = tid + i * 256;
            const int row = idx >> 2, ch = idx & 3;
            const uint32_t so = st + row * 80 + ch * 16;
            cpasync16(so,         Ahi + (size_t)(m0 + row) * lda + k0 + ch * 8);
            cpasync16(so + 10240, Alo + (size_t)(m0 + row) * lda + k0 + ch * 8);
        }
    };

    auto cvt_store = [&](char* stp, int row, int col,
                         float x0, float x1, float x2, float x3) {
        __nv_bfloat162 h01 = __floats2bfloat162_rn(x0, x1);
        __nv_bfloat162 h23 = __floats2bfloat162_rn(x2, x3);
        __nv_bfloat162 l01 = __floats2bfloat162_rn(x0 - __bfloat162float(h01.x),
                                                   x1 - __bfloat162float(h01.y));
        __nv_bfloat162 l23 = __floats2bfloat162_rn(x2 - __bfloat162float(h23.x),
                                                   x3 - __bfloat162float(h23.y));
        const int bo = row * 80 + col * 2;
        *reinterpret_cast<uint2*>(stp + bo) =
            make_uint2(*reinterpret_cast<uint32_t*>(&h01), *reinterpret_cast<uint32_t*>(&h23));
        *reinterpret_cast<uint2*>(stp + 10240 + bo) =
            make_uint2(*reinterpret_cast<uint32_t*>(&l01), *reinterpret_cast<uint32_t*>(&l23));
    };

    float av[16];
    auto ldgA = [&](int kc) {
        const int k0 = kc << 5;
#pragma unroll
        for (int i = 0; i < 4; i++) {
            const int idx = tid + i * 256;
            const int row = idx >> 3, col = (idx & 7) * 4;
            const float4 v = *reinterpret_cast<const float4*>(
                Af + (size_t)(m0 + row) * lda + k0 + col);
            av[i * 4 + 0] = v.x; av[i * 4 + 1] = v.y;
            av[i * 4 + 2] = v.z; av[i * 4 + 3] = v.w;
        }
    };
    auto storeA = [&](int kc) {
        char* stp = smem + (kc & 1) * STG;
#pragma unroll
        for (int i = 0; i < 4; i++) {
            const int idx = tid + i * 256;
            const int row = idx >> 3, col = (idx & 7) * 4;
            cvt_store(stp, row, col, av[i * 4 + 0], av[i * 4 + 1], av[i * 4 + 2], av[i * 4 + 3]);
        }
    };
    auto storeA2 = [&](int kc) {   // inline: elu(Af + Af2) -> pairs
        char* stp = smem + (kc & 1) * STG;
        const int k0 = kc << 5;
#pragma unroll
        for (int i = 0; i < 4; i++) {
            const int idx = tid + i * 256;
            const int row = idx >> 3, col = (idx & 7) * 4;
            const size_t go = (size_t)(m0 + row) * lda + k0 + col;
            const float4 v0 = *reinterpret_cast<const float4*>(Af + go);
            const float4 v1 = *reinterpret_cast<const float4*>(Af2 + go);
            cvt_store(stp, row, col,
                      eluf(v0.x + v1.x), eluf(v0.y + v1.y),
                      eluf(v0.z + v1.z), eluf(v0.w + v1.w));
        }
    };

    // ---- fragment address bases ----
    const int lane15 = lane & 15;
    const int koff = (lane >> 4) << 3;
    const uint32_t arow = (uint32_t)(warp_m * 64 + lane15);
    const uint32_t brow = (uint32_t)(warp_n * 32 + lane15);

    auto compute = [&](int kc) {
        const uint32_t stb = sb + (kc & 1) * STG;
#pragma unroll
        for (int ks = 0; ks < 32; ks += 16) {
            const uint32_t acol = (uint32_t)(ks + koff) * 2;
            uint32_t ah[4][4], al[4][4];
#pragma unroll
            for (int mf = 0; mf < 4; mf++) {
                const uint32_t ad = stb + (arow + mf * 16) * 80 + acol;
                ldsm4(ah[mf], ad);
                ldsm4(al[mf], ad + 10240);
            }
#pragma unroll
            for (int nfp = 0; nfp < 2; nfp++) {
                const uint32_t bd = stb + 20480 + (brow + nfp * 16) * 80 + acol;
                uint32_t bh[4], bl[4];
                ldsm4(bh, bd);
                ldsm4(bl, bd + 10240);
#pragma unroll
                for (int j = 0; j < 2; j++)
#pragma unroll
                    for (int mf = 0; mf < 4; mf++)
                        mma_bf16(acc[mf][nfp * 2 + j], ah[mf], bh[j], bh[2 + j]);
#pragma unroll
                for (int j = 0; j < 2; j++)
#pragma unroll
                    for (int mf = 0; mf < 4; mf++)
                        mma_bf16(acc[mf][nfp * 2 + j], ah[mf], bl[j], bl[2 + j]);
#pragma unroll
                for (int j = 0; j < 2; j++)
#pragma unroll
                    for (int mf = 0; mf < 4; mf++)
                        mma_bf16(acc[mf][nfp * 2 + j], al[mf], bh[j], bh[2 + j]);
            }
        }
    };

    // ---- pipeline (W chunk-0 issued pre-sync: overlaps predecessor tail) ----
    if (AMODE == 1) {
        issueW(0);
        if (d.pdl) grid_dep_sync();
        issueA_pairs(0); cp_commit();
        for (int kc = 0; kc < NC; kc++) {
            if (kc + 1 < NC) { issueA_pairs(kc + 1); issueW(kc + 1); cp_commit(); }
            if (kc + 1 < NC) asm volatile("cp.async.wait_group 1;" ::: "memory");
            else             asm volatile("cp.async.wait_group 0;" ::: "memory");
            __syncthreads();
            compute(kc);
            __syncthreads();
        }
    } else if (AMODE == 0) {
        ldgA(0);
        issueW(0); cp_commit();
        for (int kc = 0; kc < NC; kc++) {
            storeA(kc);
            if (kc + 1 < NC) { issueW(kc + 1); cp_commit(); }
            if (kc + 1 < NC) asm volatile("cp.async.wait_group 1;" ::: "memory");
            else             asm volatile("cp.async.wait_group 0;" ::: "memory");
            __syncthreads();
            if (kc + 1 < NC) ldgA(kc + 1);
            compute(kc);
            __syncthreads();
        }
    } else {
        issueW(0);
        if (d.pdl) grid_dep_sync();
        cp_commit();
        for (int kc = 0; kc < NC; kc++) {
            if (kc + 1 < NC) { issueW(kc + 1); cp_commit(); }
            storeA2(kc);
            if (kc + 1 < NC) asm volatile("cp.async.wait_group 1;" ::: "memory");
            else             asm volatile("cp.async.wait_group 0;" ::: "memory");
            __syncthreads();
            compute(kc);
            __syncthreads();
        }
    }

    // ---- epilogue ----
    const float* bias = (kz == 0) ? d.bias[g] : nullptr;
    const float* add  = (kz == 0) ? d.add[g] : nullptr;
    const long ldadd  = d.ldadd[g];
    const int act     = d.act[g];
    const int mode    = d.mode[g];
    const int ldc     = d.ldc[g];
    float* Cf         = d.Cf[g] + (size_t)kz * d.csplit;
    __nv_bfloat16* Chi = d.Chi[g];
    __nv_bfloat16* Clo = d.Clo[g];

    const int gid = lane >> 2;
    const int tig = lane & 3;
#pragma unroll
    for (int mf = 0; mf < 4; mf++) {
        const int r0 = m0 + warp_m * 64 + mf * 16 + gid;
#pragma unroll
        for (int nf = 0; nf < 4; nf++) {
            const int coll = nl0 + warp_n * 32 + nf * 8 + tig * 2;
            float v0 = acc[mf][nf][0], v1 = acc[mf][nf][1];
            float v2 = acc[mf][nf][2], v3 = acc[mf][nf][3];
            if (bias) {
                const float b0v = bias[coll], b1v = bias[coll + 1];
                v0 += b0v; v1 += b1v; v2 += b0v; v3 += b1v;
            }
            if (add) {
                const float2 a0 = *reinterpret_cast<const float2*>(add + (size_t)r0 * ldadd + coll);
                const float2 a1 = *reinterpret_cast<const float2*>(add + (size_t)(r0 + 8) * ldadd + coll);
                v0 += a0.x; v1 += a0.y; v2 += a1.x; v3 += a1.y;
            }
            if (act) { v0 = eluf(v0); v1 = eluf(v1); v2 = eluf(v2); v3 = eluf(v3); }
            if (mode == 0) {
                *reinterpret_cast<float2*>(Cf + (size_t)r0 * ldc + coll)       = make_float2(v0, v1);
                *reinterpret_cast<float2*>(Cf + (size_t)(r0 + 8) * ldc + coll) = make_float2(v2, v3);
            } else {
                __nv_bfloat162 h0 = __floats2bfloat162_rn(v0, v1);
                __nv_bfloat162 l0 = __floats2bfloat162_rn(v0 - __bfloat162float(h0.x),
                                                          v1 - __bfloat162float(h0.y));
                __nv_bfloat162 h1 = __floats2bfloat162_rn(v2, v3);
                __nv_bfloat162 l1 = __floats2bfloat162_rn(v2 - __bfloat162float(h1.x),
                                                          v3 - __bfloat162float(h1.y));
                *reinterpret_cast<uint32_t*>(Chi + (size_t)r0 * ldc + coll)       = *reinterpret_cast<uint32_t*>(&h0);
                *reinterpret_cast<uint32_t*>(Clo + (size_t)r0 * ldc + coll)       = *reinterpret_cast<uint32_t*>(&l0);
                *reinterpret_cast<uint32_t*>(Chi + (size_t)(r0 + 8) * ldc + coll) = *reinterpret_cast<uint32_t*>(&h1);
                *reinterpret_cast<uint32_t*>(Clo + (size_t)(r0 + 8) * ldc + coll) = *reinterpret_cast<uint32_t*>(&l1);
            }
        }
    }
}

// ---------------------------------------------------------------------------
// Single init kernel: pack all weights (hi/lo), Wih^T, W2^T, zero h
// ---------------------------------------------------------------------------
struct PackArgs {
    const float* src[14];
    int ld[14];
    int coff[14];
    const float* wih;
};
__constant__ int c_seg_off[15] = {
    OFF_encW0, OFF_encW1, OFF_encW2, OFF_posW0e, OFF_posW0h, OFF_priW0,
    OFF_gruWhh, OFF_priW1, OFF_posW1, OFF_priW2, OFF_posW2, OFF_decW0,
    OFF_decW1, OFF_decW2, WTOT
};
__constant__ int c_seg_K[14] = {
    256, 512, 512, 512, 512, 512, 512, 512, 512, 512, 512, 64, 512, 512
};

#define PACK_EXTRA (64 * 1536 + B_ * 512 + 512 * 256)
__global__ void pack_all(PackArgs a) {
    const int i = blockIdx.x * 256 + threadIdx.x;
    if (i < WTOT) {
        int s = 0;
        while (s + 1 < 14 && i >= c_seg_off[s + 1]) s++;
        const int li = i - c_seg_off[s];
        const int K = c_seg_K[s];
        const int r = li / K, k = li - r * K;
        const float v = a.src[s][(size_t)r * a.ld[s] + a.coff[s] + k];
        const __nv_bfloat16 h = __float2bfloat16(v);
        g_whi[i] = h;
        g_wlo[i] = __float2bfloat16(v - __bfloat162float(h));
    } else if (i < WTOT + 64 * 1536) {
        const int li = i - WTOT;
        const int row = li / 64, k = li - row * 64;
        g_wiht[k * 1536 + row] = a.wih[li];
    } else if (i < WTOT + 64 * 1536 + B_ * 512) {
        const int li = i - WTOT - 64 * 1536;
        g_h[li] = 0.f;
        g_h_hi[li] = __float2bfloat16(0.f);
        g_h_lo[li] = __float2bfloat16(0.f);
    } else if (i < WTOT + 64 * 1536 + B_ * 512 + 512 * 256) {
        const int li = i - WTOT - 64 * 1536 - B_ * 512;
        const int k = li >> 8, c = li & 255;
        g_w2t[li] = (c < 128) ? a.src[9][(size_t)c * 512 + k]
                              : a.src[10][(size_t)(c - 128) * 512 + k];
    }
}

// ---------------------------------------------------------------------------
// Fused S3 + latent + GRU kernel (per timestep).
// ---------------------------------------------------------------------------
#define TMB 8
#define A1_PB ((size_t)B_ * 1024)
#define S1_PB ((size_t)B_ * 2560)
__global__ void __launch_bounds__(512) s3_gru_kernel(
    const float* __restrict__ eps,
    const float* __restrict__ bih,
    const float* __restrict__ pri_b2,
    const float* __restrict__ pos_b2,
    float* __restrict__ kls_out,
    float* __restrict__ mu_out,
    int t)
{
    __shared__ __align__(16) float sA[TMB][1024];
    __shared__ float s_out2[TMB][256];
    __shared__ float zs[TMB][64];
    __shared__ float klw[TMB][2];

    const int m0 = blockIdx.x * TMB;
    const int tid = threadIdx.x;   // 512 threads

    grid_dep_sync();

    // ---- Phase 1: sA = elu(sum of 4 S2 partials) ----
    {
#pragma unroll
        for (int i = 0; i < 4; i++) {
            const int idx = tid + i * 512;
            const int row = idx >> 8, c4 = (idx & 255) * 4;
            const size_t go = (size_t)(m0 + row) * 1024 + c4;
            const float4 v0 = *reinterpret_cast<const float4*>(g_a1p + go);
            const float4 v1 = *reinterpret_cast<const float4*>(g_a1p + A1_PB + go);
            const float4 v2 = *reinterpret_cast<const float4*>(g_a1p + 2 * A1_PB + go);
            const float4 v3 = *reinterpret_cast<const float4*>(g_a1p + 3 * A1_PB + go);
            sA[row][c4 + 0] = eluf(v0.x + v1.x + v2.x + v3.x);
            sA[row][c4 + 1] = eluf(v0.y + v1.y + v2.y + v3.y);
            sA[row][c4 + 2] = eluf(v0.z + v1.z + v2.z + v3.z);
            sA[row][c4 + 3] = eluf(v0.w + v1.w + v2.w + v3.w);
        }
    }
    __syncthreads();

    // ---- Phase 2: out2[r][c] = sum_k A[r][aoff+k] * W2t[k][c]  (split-k x2) ----
    {
        const int c = tid & 255;
        const int kh = tid >> 8;
        const int aoff = ((c < 128) ? 0 : 512) + kh * 256;
        const float* wp = g_w2t + (size_t)(kh * 256) * 256 + c;
        float accs[TMB];
#pragma unroll
        for (int r = 0; r < TMB; r++) accs[r] = 0.f;
#pragma unroll 4
        for (int kk = 0; kk < 64; kk++) {
            const float w0 = wp[(kk * 4 + 0) * 256];
            const float w1 = wp[(kk * 4 + 1) * 256];
            const float w2 = wp[(kk * 4 + 2) * 256];
            const float w3 = wp[(kk * 4 + 3) * 256];
#pragma unroll
            for (int r = 0; r < TMB; r++) {
                const float4 av = *reinterpret_cast<const float4*>(&sA[r][aoff + kk * 4]);
                accs[r] = fmaf(av.x, w0, fmaf(av.y, w1, fmaf(av.z, w2, fmaf(av.w, w3, accs[r]))));
            }
        }
        if (kh == 1) {
#pragma unroll
            for (int r = 0; r < TMB; r++) s_out2[r][c] = accs[r];
        }
        __syncthreads();
        if (kh == 0) {
            const float b = (c < 128) ? pri_b2[c] : pos_b2[c - 128];
#pragma unroll
            for (int r = 0; r < TMB; r++) s_out2[r][c] = accs[r] + s_out2[r][c] + b;
        }
        __syncthreads();
    }

    // ---- Phase 3: latent sample + KL + mu ----
    {
        const int r = tid >> 6, k = tid & 63;
        const int m = m0 + r;
        const float mu_p = s_out2[r][k];
        const float ls_p = s_out2[r][64 + k];
        const float mu_q = s_out2[r][128 + k];
        const float ls_q = s_out2[r][192 + k];
        const float e = eps[((size_t)m * T_ + t) * 64 + k];
        const float zl = fmaf(expf(ls_q), e, mu_q);
        zs[r][k] = zl;
        const __nv_bfloat16 zh = __float2bfloat16(zl);
        g_z_hi[((size_t)m * T_ + t) * 64 + k] = zh;
        g_z_lo[((size_t)m * T_ + t) * 64 + k] = __float2bfloat16(zl - __bfloat162float(zh));
        mu_out[((size_t)m * T_ + t) * 64 + k] = mu_q;
        const float dm = mu_q - mu_p;
        float klv = ls_p - ls_q + (expf(2.f * ls_q) + dm * dm) / (2.f * expf(2.f * ls_p)) - 0.5f;
#pragma unroll
        for (int off = 16; off > 0; off >>= 1)
            klv += __shfl_down_sync(0xffffffffu, klv, off);
        if ((tid & 31) == 0) klw[r][(tid >> 5) & 1] = klv;
    }
    __syncthreads();
    if (tid < TMB) kls_out[(size_t)(m0 + tid) * T_ + t] = klw[tid][0] + klw[tid][1];

    // ---- Phase 4: GRU gates + h update (gh = sum of 2 partials) ----
    {
        const int j = tid;
        float ar[TMB], az[TMB], an[TMB];
#pragma unroll
        for (int r = 0; r < TMB; r++) { ar[r] = 0.f; az[r] = 0.f; an[r] = 0.f; }

#pragma unroll 4
        for (int k = 0; k < 64; k++) {
            const float wr = g_wiht[k * 1536 + j];
            const float wz = g_wiht[k * 1536 + 512 + j];
            const float wn = g_wiht[k * 1536 + 1024 + j];
#pragma unroll
            for (int r = 0; r < TMB; r++) {
                const float zk = zs[r][k];
                ar[r] = fmaf(zk, wr, ar[r]);
                az[r] = fmaf(zk, wz, az[r]);
                an[r] = fmaf(zk, wn, an[r]);
            }
        }

        const float br = bih[j], bz = bih[512 + j], bn = bih[1024 + j];
#pragma unroll
        for (int r = 0; r < TMB; r++) {
            const int m = m0 + r;
            const float* g0 = g_s1p + (size_t)m * 2560 + 1024;
            const float ghr = g0[j]        + g0[S1_PB + j];
            const float ghz = g0[512 + j]  + g0[S1_PB + 512 + j];
            const float ghn = g0[1024 + j] + g0[S1_PB + 1024 + j];
            const float rg = 1.f / (1.f + expf(-(ar[r] + br + ghr)));
            const float zg = 1.f / (1.f + expf(-(az[r] + bz + ghz)));
            const float ng = tanhf(an[r] + bn + rg * ghn);
            const float hv = g_h[(size_t)m * 512 + j];
            const float hn = (1.f - zg) * ng + zg * hv;
            g_h[(size_t)m * 512 + j] = hn;
            const __nv_bfloat16 hh = __float2bfloat16(hn);
            g_h_hi[(size_t)m * 512 + j] = hh;
            g_h_lo[(size_t)m * 512 + j] = __float2bfloat16(hn - __bfloat162float(hh));
        }
    }
}

// ---------------------------------------------------------------------------
// Host helpers
// ---------------------------------------------------------------------------
static inline GemmTC make_desc(int K, int ksplit = 1, long csplit = 0) {
    GemmTC d{};
    d.K = K; d.ng = 0; d.n_off[0] = 0;
    d.ksplit = ksplit; d.csplit = csplit; d.pdl = 0;
    return d;
}
static inline void add_group(GemmTC& d, int nsub,
                             const float* Af, const float* Af2,
                             const __nv_bfloat16* Ahi, const __nv_bfloat16* Alo, int lda,
                             const __nv_bfloat16* Whi, const __nv_bfloat16* Wlo,
                             const float* bias, const float* add, long ldadd, int act,
                             int mode, float* Cf, __nv_bfloat16* Chi, __nv_bfloat16* Clo, int ldc) {
    const int g = d.ng;
    d.Af[g] = Af; d.Af2[g] = Af2; d.Ahi[g] = Ahi; d.Alo[g] = Alo; d.lda[g] = lda;
    d.Whi[g] = Whi; d.Wlo[g] = Wlo;
    d.bias[g] = bias; d.add[g] = add; d.ldadd[g] = ldadd;
    d.act[g] = act; d.mode[g] = mode;
    d.Cf[g] = Cf; d.Chi[g] = Chi; d.Clo[g] = Clo; d.ldc[g] = ldc;
    d.n_off[g + 1] = d.n_off[g] + nsub;
    d.ng = g + 1;
}

// Launch a GEMM with the PDL attribute set.
template <int AMODE>
static inline void launch_pdl(dim3 grid, GemmTC& d) {
    d.pdl = 1;
    cudaLaunchConfig_t cfg{};
    cfg.gridDim = grid; cfg.blockDim = dim3(256);
    cfg.dynamicSmemBytes = SMEM_DYN; cfg.stream = 0;
    cudaLaunchAttribute at[1];
    at[0].id = cudaLaunchAttributeProgrammaticStreamSerialization;
    at[0].val.programmaticStreamSerializationAllowed = 1;
    cfg.attrs = at; cfg.numAttrs = 1;
    cudaLaunchKernelEx(&cfg, gemm_tc<AMODE>, d);
}
static inline void launch_s3_pdl(const float* eps, const float* bih,
                                 const float* pb2, const float* qb2,
                                 float* kls, float* mu, int t) {
    cudaLaunchConfig_t cfg{};
    cfg.gridDim = dim3(B_ / TMB); cfg.blockDim = dim3(512);
    cfg.dynamicSmemBytes = 0; cfg.stream = 0;
    cudaLaunchAttribute at[1];
    at[0].id = cudaLaunchAttributeProgrammaticStreamSerialization;
    at[0].val.programmaticStreamSerializationAllowed = 1;
    cfg.attrs = at; cfg.numAttrs = 1;
    cudaLaunchKernelEx(&cfg, s3_gru_kernel, eps, bih, pb2, qb2, kls, mu, t);
}

extern "C" void kernel_launch(void* const* d_in, const int* in_sizes, int n_in,
                              void* d_out, int out_size) {
    const float* obs     = (const float*)d_in[0];
    const float* eps     = (const float*)d_in[1];
    const float* enc_W0  = (const float*)d_in[2];
    const float* enc_b0  = (const float*)d_in[3];
    const float* enc_W1  = (const float*)d_in[4];
    const float* enc_b1  = (const float*)d_in[5];
    const float* enc_W2  = (const float*)d_in[6];
    const float* enc_b2  = (const float*)d_in[7];
    const float* pri_W0  = (const float*)d_in[8];
    const float* pri_b0  = (const float*)d_in[9];
    const float* pri_W1  = (const float*)d_in[10];
    const float* pri_b1  = (const float*)d_in[11];
    const float* pri_W2  = (const float*)d_in[12];
    const float* pri_b2  = (const float*)d_in[13];
    const float* pos_W0  = (const float*)d_in[14];
    const float* pos_b0  = (const float*)d_in[15];
    const float* pos_W1  = (const float*)d_in[16];
    const float* pos_b1  = (const float*)d_in[17];
    const float* pos_W2  = (const float*)d_in[18];
    const float* pos_b2  = (const float*)d_in[19];
    const float* dec_W0  = (const float*)d_in[20];
    const float* dec_b0  = (const float*)d_in[21];
    const float* dec_W1  = (const float*)d_in[22];
    const float* dec_b1  = (const float*)d_in[23];
    const float* dec_W2  = (const float*)d_in[24];
    const float* dec_b2  = (const float*)d_in[25];
    const float* gru_Wih = (const float*)d_in[26];
    const float* gru_bih = (const float*)d_in[27];
    const float* gru_Whh = (const float*)d_in[28];
    const float* gru_bhh = (const float*)d_in[29];
    (void)in_sizes; (void)n_in; (void)out_size;

    __nv_bfloat16 *bufA_hi, *bufA_lo, *bufB_hi, *bufB_lo, *z_hi, *z_lo;
    __nv_bfloat16 *whi, *wlo, *h_hi, *h_lo;
    float *posc, *s1p, *a1p;
    cudaGetSymbolAddress((void**)&bufA_hi, g_bufA_hi);
    cudaGetSymbolAddress((void**)&bufA_lo, g_bufA_lo);
    cudaGetSymbolAddress((void**)&bufB_hi, g_bufB_hi);
    cudaGetSymbolAddress((void**)&bufB_lo, g_bufB_lo);
    cudaGetSymbolAddress((void**)&z_hi,    g_z_hi);
    cudaGetSymbolAddress((void**)&z_lo,    g_z_lo);
    cudaGetSymbolAddress((void**)&posc,    g_posc);
    cudaGetSymbolAddress((void**)&whi,     g_whi);
    cudaGetSymbolAddress((void**)&wlo,     g_wlo);
    cudaGetSymbolAddress((void**)&s1p,     g_s1p);
    cudaGetSymbolAddress((void**)&a1p,     g_a1p);
    cudaGetSymbolAddress((void**)&h_hi,    g_h_hi);
    cudaGetSymbolAddress((void**)&h_lo,    g_h_lo);

    cudaFuncSetAttribute(gemm_tc<0>, cudaFuncAttributeMaxDynamicSharedMemorySize, SMEM_DYN);
    cudaFuncSetAttribute(gemm_tc<1>, cudaFuncAttributeMaxDynamicSharedMemorySize, SMEM_DYN);
    cudaFuncSetAttribute(gemm_tc<2>, cudaFuncAttributeMaxDynamicSharedMemorySize, SMEM_DYN);

    float* recons = (float*)d_out;
    float* kls    = recons + (size_t)BT_ * OBS_;
    float* mu     = kls + BT_;

    // ---- single init/pack launch ----
    PackArgs pa;
    const float* srcs[14] = { enc_W0, enc_W1, enc_W2, pos_W0, pos_W0, pri_W0, gru_Whh,
                              pri_W1, pos_W1, pri_W2, pos_W2, dec_W0, dec_W1, dec_W2 };
    const int lds[14]   = { 256, 512, 512, 1024, 1024, 512, 512, 512, 512, 512, 512, 64, 512, 512 };
    const int coffs[14] = { 0, 0, 0, 512, 0, 0, 0, 0, 0, 0, 0, 0, 0, 0 };
    for (int i = 0; i < 14; i++) { pa.src[i] = srcs[i]; pa.ld[i] = lds[i]; pa.coff[i] = coffs[i]; }
    pa.wih = gru_Wih;
    pack_all<<<(WTOT + PACK_EXTRA + 255) / 256, 256>>>(pa);

    // ---- Encoder chain (parallel over B*T) ----
    {
        GemmTC d = make_desc(256);
        add_group(d, 512, obs, nullptr, nullptr, nullptr, 256, whi + OFF_encW0, wlo + OFF_encW0,
                  enc_b0, nullptr, 0, 1, 1, nullptr, bufA_hi, bufA_lo, 512);
        gemm_tc<0><<<dim3(4, BT_ / 128), 256, SMEM_DYN>>>(d);
    }
    {
        GemmTC d = make_desc(512);
        add_group(d, 512, nullptr, nullptr, bufA_hi, bufA_lo, 512, whi + OFF_encW1, wlo + OFF_encW1,
                  enc_b1, nullptr, 0, 1, 1, nullptr, bufB_hi, bufB_lo, 512);
        launch_pdl<1>(dim3(4, BT_ / 128), d);
    }
    {
        GemmTC d = make_desc(512);
        add_group(d, 512, nullptr, nullptr, bufB_hi, bufB_lo, 512, whi + OFF_encW2, wlo + OFF_encW2,
                  enc_b2, nullptr, 0, 0, 1, nullptr, bufA_hi, bufA_lo, 512);
        launch_pdl<1>(dim3(4, BT_ / 128), d);
    }
    {
        GemmTC d = make_desc(512);
        add_group(d, 512, nullptr, nullptr, bufA_hi, bufA_lo, 512, whi + OFF_posW0e, wlo + OFF_posW0e,
                  pos_b0, nullptr, 0, 0, 0, posc, nullptr, nullptr, 512);
        launch_pdl<1>(dim3(4, BT_ / 128), d);
    }

    // ---- Sequential recurrence (3 PDL launches per step, R11 shapes) ----
    for (int t = 0; t < T_; t++) {
        // S1: h -> [pri_a0 | pos_a0 | gh] fp32 partials, split-K x2
        {
            GemmTC d = make_desc(512, 2, (long)B_ * 2560);
            add_group(d, 512, nullptr, nullptr, h_hi, h_lo, 512, whi + OFF_priW0, wlo + OFF_priW0,
                      pri_b0, nullptr, 0, 0, 0, s1p, nullptr, nullptr, 2560);
            add_group(d, 512, nullptr, nullptr, h_hi, h_lo, 512, whi + OFF_posW0h, wlo + OFF_posW0h,
                      nullptr, posc + (size_t)t * 512, (long)T_ * 512, 0,
                      0, s1p + 512, nullptr, nullptr, 2560);
            add_group(d, 1536, nullptr, nullptr, h_hi, h_lo, 512, whi + OFF_gruWhh, wlo + OFF_gruWhh,
                      gru_bhh, nullptr, 0, 0, 0, s1p + 1024, nullptr, nullptr, 2560);
            launch_pdl<1>(dim3(20, 8, 2), d);
        }
        // S2: A = elu(s1p0 + s1p1), fp32 partials out, split-K x4
        {
            GemmTC d = make_desc(512, 4, (long)B_ * 1024);
            add_group(d, 512, s1p, s1p + (size_t)B_ * 2560, nullptr, nullptr, 2560,
                      whi + OFF_priW1, wlo + OFF_priW1,
                      pri_b1, nullptr, 0, 0, 0, a1p, nullptr, nullptr, 1024);
            add_group(d, 512, s1p + 512, s1p + (size_t)B_ * 2560 + 512, nullptr, nullptr, 2560,
                      whi + OFF_posW1, wlo + OFF_posW1,
                      pos_b1, nullptr, 0, 0, 0, a1p + 512, nullptr, nullptr, 1024);
            launch_pdl<2>(dim3(8, 8, 4), d);
        }
        // S3 + latent + GRU fused (PDL)
        launch_s3_pdl(eps, gru_bih, pri_b2, pos_b2, kls, mu, t);
    }

    // ---- Deferred decoder over all (B*T) rows ----
    {
        GemmTC d = make_desc(64);
        add_group(d, 512, nullptr, nullptr, z_hi, z_lo, 64, whi + OFF_decW0, wlo + OFF_decW0,
                  dec_b0, nullptr, 0, 1, 1, nullptr, bufA_hi, bufA_lo, 512);
        launch_pdl<1>(dim3(4, BT_ / 128), d);
    }
    {
        GemmTC d = make_desc(512);
        add_group(d, 512, nullptr, nullptr, bufA_hi, bufA_lo, 512, whi + OFF_decW1, wlo + OFF_decW1,
                  dec_b1, nullptr, 0, 1, 1, nullptr, bufB_hi, bufB_lo, 512);
        launch_pdl<1>(dim3(4, BT_ / 128), d);
    }
    {
        GemmTC d = make_desc(512);
        add_group(d, 256, nullptr, nullptr, bufB_hi, bufB_lo, 512, whi + OFF_decW2, wlo + OFF_decW2,
                  dec_b2, nullptr, 0, 0, 0, recons, nullptr, nullptr, 256);
        launch_pdl<1>(dim3(2, BT_ / 128), d);
    }
}